// round 2
// baseline (speedup 1.0000x reference)
#include <cuda_runtime.h>

#define N_TOK 343
#define EMBED 192
#define HEADS 6
#define HD 32
#define BATCH 256
#define NWIN 64
#define QSCALE 0.17677669529663687f  /* 32^-0.5 */

#define M_ROWS (BATCH * N_TOK)        /* 87808 = 1372*64 */
#define SMEM_ATTN (2 * 344 * 32 * 4)  /* K + V tiles, padded to 344 rows */

typedef unsigned long long f32x2_t;

// ---------------- packed f32x2 primitives (B300 FFMA2 path) ----------------
__device__ __forceinline__ f32x2_t pk(float lo, float hi) {
    f32x2_t r;
    asm("mov.b64 %0, {%1, %2};" : "=l"(r) : "f"(lo), "f"(hi));
    return r;
}
__device__ __forceinline__ float2 unpk(f32x2_t v) {
    float2 r;
    asm("mov.b64 {%0, %1}, %2;" : "=f"(r.x), "=f"(r.y) : "l"(v));
    return r;
}
__device__ __forceinline__ void fma2(f32x2_t& d, f32x2_t a, f32x2_t b) {
    asm("fma.rn.f32x2 %0, %1, %2, %0;" : "+l"(d) : "l"(a), "l"(b));
}
__device__ __forceinline__ void mul2i(f32x2_t& d, f32x2_t a) {
    asm("mul.rn.f32x2 %0, %0, %1;" : "+l"(d) : "l"(a));
}
__device__ __forceinline__ f32x2_t add2(f32x2_t a, f32x2_t b) {
    f32x2_t r;
    asm("add.rn.f32x2 %0, %1, %2;" : "=l"(r) : "l"(a), "l"(b));
    return r;
}

// ---------------- scratch (device globals: no allocations allowed) ----------
__device__ float g_q[BATCH * HEADS * N_TOK * HD];     // [b,h,n,d]
__device__ float g_k[BATCH * HEADS * N_TOK * HD];
__device__ float g_v[BATCH * HEADS * N_TOK * HD];
__device__ float g_ctx[BATCH * N_TOK * EMBED];        // [b,n,c]
__device__ float g_bias[HEADS * N_TOK * N_TOK];       // [h,q,k]

// ---------------- bias gather: bias[h,q,k] = table[rel_idx[q,k], h] --------
__global__ void bias_gather_kernel(const float* __restrict__ table,
                                   const int* __restrict__ rel) {
    int i = blockIdx.x * blockDim.x + threadIdx.x;
    if (i >= N_TOK * N_TOK) return;
    int r = rel[i];
#pragma unroll
    for (int h = 0; h < HEADS; ++h)
        g_bias[h * N_TOK * N_TOK + i] = table[r * HEADS + h];
}

// ---------------- shared GEMM core: C[m,n] = sum_k A[m,k]*W[n,k] ------------
// BM=BN=64, BK=32, 256 threads, 4x4 per thread (packed 4x2 f32x2 acc).
__device__ __forceinline__ void gemm_core(const float* __restrict__ A,
                                          const float* __restrict__ W,
                                          int m0, int n0, int tid,
                                          float* As, float* Bs,
                                          f32x2_t acc2[4][2]) {
    const int tx = tid & 15, ty = tid >> 4;
#pragma unroll 1
    for (int kt = 0; kt < 6; ++kt) {
        const int k0 = kt * 32;
#pragma unroll
        for (int r = 0; r < 2; ++r) {
            int idx = tid + 256 * r;
            int row = idx >> 3, c4 = idx & 7;
            float4 av = *(const float4*)(A + (size_t)(m0 + row) * EMBED + k0 + c4 * 4);
            float4 wv = *(const float4*)(W + (size_t)(n0 + row) * EMBED + k0 + c4 * 4);
            int kb = c4 * 4;
            As[(kb + 0) * 68 + row] = av.x;
            As[(kb + 1) * 68 + row] = av.y;
            As[(kb + 2) * 68 + row] = av.z;
            As[(kb + 3) * 68 + row] = av.w;
            Bs[(kb + 0) * 68 + row] = wv.x;
            Bs[(kb + 1) * 68 + row] = wv.y;
            Bs[(kb + 2) * 68 + row] = wv.z;
            Bs[(kb + 3) * 68 + row] = wv.w;
        }
        __syncthreads();
#pragma unroll
        for (int kk = 0; kk < 32; ++kk) {
            float4 a4 = *(const float4*)(As + kk * 68 + ty * 4);
            ulonglong2 b2 = *(const ulonglong2*)(Bs + kk * 68 + tx * 4);
            f32x2_t ad;
            ad = pk(a4.x, a4.x);
            fma2(acc2[0][0], ad, b2.x); fma2(acc2[0][1], ad, b2.y);
            ad = pk(a4.y, a4.y);
            fma2(acc2[1][0], ad, b2.x); fma2(acc2[1][1], ad, b2.y);
            ad = pk(a4.z, a4.z);
            fma2(acc2[2][0], ad, b2.x); fma2(acc2[2][1], ad, b2.y);
            ad = pk(a4.w, a4.w);
            fma2(acc2[3][0], ad, b2.x); fma2(acc2[3][1], ad, b2.y);
        }
        __syncthreads();
    }
}

// ---------------- fused Q + KV projections ----------------------------------
// grid.y in [0,9): y<3 -> Q (x_in @ q_w^T * scale), else KV (x_cross @ kv_w^T)
__global__ __launch_bounds__(256) void gemm_qkv_kernel(
    const float* __restrict__ x_in, const float* __restrict__ x_cross,
    const float* __restrict__ q_w, const float* __restrict__ kv_w) {
    __shared__ float As[32 * 68];
    __shared__ float Bs[32 * 68];
    const int tid = threadIdx.x;
    const int m0 = blockIdx.x * 64;
    const int yt = blockIdx.y;
    const bool isq = (yt < 3);
    const float* A = isq ? x_in : x_cross;
    const float* W = isq ? q_w : kv_w;
    const int n0 = isq ? yt * 64 : (yt - 3) * 64;

    f32x2_t acc2[4][2];
#pragma unroll
    for (int i = 0; i < 4; ++i) { acc2[i][0] = 0ULL; acc2[i][1] = 0ULL; }

    gemm_core(A, W, m0, n0, tid, As, Bs, acc2);

    const int tx = tid & 15, ty = tid >> 4;
#pragma unroll
    for (int i = 0; i < 4; ++i) {
        int m = m0 + ty * 4 + i;
        int bb = m / N_TOK;
        int nn = m - bb * N_TOK;
        float vals[4];
        float2 u0 = unpk(acc2[i][0]);
        float2 u1 = unpk(acc2[i][1]);
        vals[0] = u0.x; vals[1] = u0.y; vals[2] = u1.x; vals[3] = u1.y;
#pragma unroll
        for (int j = 0; j < 4; ++j) {
            int n = n0 + tx * 4 + j;
            float v = vals[j];
            if (isq) {
                int h = n >> 5, d = n & 31;
                g_q[((size_t)(bb * HEADS + h) * N_TOK + nn) * HD + d] = v * QSCALE;
            } else {
                int nc = (n < EMBED) ? n : n - EMBED;
                float* dst = (n < EMBED) ? g_k : g_v;
                int h = nc >> 5, d = nc & 31;
                dst[((size_t)(bb * HEADS + h) * N_TOK + nn) * HD + d] = v;
            }
        }
    }
}

// ---------------- output projection: out = ctx @ proj_w^T + proj_b ---------
__global__ __launch_bounds__(256) void gemm_proj_kernel(
    const float* __restrict__ proj_w, const float* __restrict__ proj_b,
    float* __restrict__ out) {
    __shared__ float As[32 * 68];
    __shared__ float Bs[32 * 68];
    const int tid = threadIdx.x;
    const int m0 = blockIdx.x * 64;
    const int n0 = blockIdx.y * 64;

    f32x2_t acc2[4][2];
#pragma unroll
    for (int i = 0; i < 4; ++i) { acc2[i][0] = 0ULL; acc2[i][1] = 0ULL; }

    gemm_core(g_ctx, proj_w, m0, n0, tid, As, Bs, acc2);

    const int tx = tid & 15, ty = tid >> 4;
#pragma unroll
    for (int i = 0; i < 4; ++i) {
        int m = m0 + ty * 4 + i;
        float vals[4];
        float2 u0 = unpk(acc2[i][0]);
        float2 u1 = unpk(acc2[i][1]);
        vals[0] = u0.x; vals[1] = u0.y; vals[2] = u1.x; vals[3] = u1.y;
#pragma unroll
        for (int j = 0; j < 4; ++j) {
            int n = n0 + tx * 4 + j;
            out[(size_t)m * EMBED + n] = vals[j] + proj_b[n];
        }
    }
}

// ---------------- flash attention per (b, h) --------------------------------
// 352 threads; one thread per q-row; K,V [344x32] in dynamic smem (row 343=0).
// Online softmax, chunk=8; inner products in packed f32x2.
__global__ __launch_bounds__(352, 2) void attn_kernel(const float* __restrict__ mask) {
    extern __shared__ float sm[];
    float* Ks = sm;             // 344*32
    float* Vs = sm + 344 * 32;  // 344*32
    const int bh = blockIdx.x;
    const int b = bh / HEADS;
    const int h = bh - b * HEADS;
    const int w = b & (NWIN - 1);
    const int tid = threadIdx.x;

    const float4* Ksrc = (const float4*)(g_k + (size_t)bh * N_TOK * HD);
    const float4* Vsrc = (const float4*)(g_v + (size_t)bh * N_TOK * HD);
    float4* Kd = (float4*)Ks;
    float4* Vd = (float4*)Vs;
    const float4 z4 = make_float4(0.f, 0.f, 0.f, 0.f);
    for (int i = tid; i < 344 * 8; i += 352) {
        Kd[i] = (i < N_TOK * 8) ? Ksrc[i] : z4;
        Vd[i] = (i < N_TOK * 8) ? Vsrc[i] : z4;
    }
    __syncthreads();

    const int q = tid;
    if (q < N_TOK) {
        f32x2_t qv[16];
        const ulonglong2* qsrc = (const ulonglong2*)(g_q + ((size_t)bh * N_TOK + q) * HD);
#pragma unroll
        for (int c = 0; c < 8; ++c) {
            ulonglong2 t = qsrc[c];
            qv[2 * c] = t.x; qv[2 * c + 1] = t.y;
        }

        const float* brow = g_bias + ((size_t)h * N_TOK + q) * N_TOK;
        const float* mrow = mask + ((size_t)w * N_TOK + q) * N_TOK;

        const ulonglong2* K2 = (const ulonglong2*)Ks;
        const ulonglong2* V2 = (const ulonglong2*)Vs;

        float mrun = -1e30f, l = 0.f;
        f32x2_t acc[16];
#pragma unroll
        for (int c = 0; c < 16; ++c) acc[c] = 0ULL;

#pragma unroll 1
        for (int k0 = 0; k0 < N_TOK; k0 += 8) {
            float s[8];
#pragma unroll
            for (int j = 0; j < 8; ++j) {
                int k = k0 + j;
                f32x2_t sa = 0ULL, sb = 0ULL;
#pragma unroll
                for (int c = 0; c < 4; ++c) {
                    ulonglong2 kv0 = K2[k * 8 + 2 * c];
                    ulonglong2 kv1 = K2[k * 8 + 2 * c + 1];
                    fma2(sa, qv[4 * c + 0], kv0.x);
                    fma2(sb, qv[4 * c + 1], kv0.y);
                    fma2(sa, qv[4 * c + 2], kv1.x);
                    fma2(sb, qv[4 * c + 3], kv1.y);
                }
                float2 sp = unpk(add2(sa, sb));
                if (k < N_TOK) s[j] = (sp.x + sp.y) + brow[k] + mrow[k];
                else           s[j] = -1e30f;
            }
            float mc = s[0];
#pragma unroll
            for (int j = 1; j < 8; ++j) mc = fmaxf(mc, s[j]);
            float newm = fmaxf(mrun, mc);
            float alpha = __expf(mrun - newm);
            l *= alpha;
            f32x2_t am = pk(alpha, alpha);
#pragma unroll
            for (int c = 0; c < 16; ++c) mul2i(acc[c], am);
#pragma unroll
            for (int j = 0; j < 8; ++j) {
                float p = __expf(s[j] - newm);
                l += p;
                f32x2_t pd = pk(p, p);
#pragma unroll
                for (int c = 0; c < 8; ++c) {
                    ulonglong2 vv = V2[(k0 + j) * 8 + c];
                    fma2(acc[2 * c], pd, vv.x);
                    fma2(acc[2 * c + 1], pd, vv.y);
                }
            }
            mrun = newm;
        }

        float inv = __fdividef(1.f, l);
        f32x2_t iv = pk(inv, inv);
        ulonglong2* dst = (ulonglong2*)(g_ctx + ((size_t)(b * N_TOK + q)) * EMBED + h * HD);
#pragma unroll
        for (int c = 0; c < 8; ++c) {
            mul2i(acc[2 * c], iv);
            mul2i(acc[2 * c + 1], iv);
            ulonglong2 o;
            o.x = acc[2 * c]; o.y = acc[2 * c + 1];
            dst[c] = o;
        }
    }
}

// ---------------- launch -----------------------------------------------------
extern "C" void kernel_launch(void* const* d_in, const int* in_sizes, int n_in,
                              void* d_out, int out_size) {
    const float* x_in    = (const float*)d_in[0];
    const float* x_cross = (const float*)d_in[1];
    const float* mask    = (const float*)d_in[2];
    const float* q_w     = (const float*)d_in[3];
    const float* kv_w    = (const float*)d_in[4];
    const float* proj_w  = (const float*)d_in[5];
    const float* proj_b  = (const float*)d_in[6];
    const float* table   = (const float*)d_in[7];
    const int*   rel     = (const int*)d_in[8];
    float* out = (float*)d_out;

    cudaFuncSetAttribute(attn_kernel,
                         cudaFuncAttributeMaxDynamicSharedMemorySize, SMEM_ATTN);

    bias_gather_kernel<<<(N_TOK * N_TOK + 255) / 256, 256>>>(table, rel);
    gemm_qkv_kernel<<<dim3(M_ROWS / 64, 9), 256>>>(x_in, x_cross, q_w, kv_w);
    attn_kernel<<<BATCH * HEADS, 352, SMEM_ATTN>>>(mask);
    gemm_proj_kernel<<<dim3(M_ROWS / 64, 3), 256>>>(proj_w, proj_b, out);
}

// round 3
// speedup vs baseline: 1.2137x; 1.2137x over previous
#include <cuda_runtime.h>

#define N_TOK 343
#define EMBED 192
#define HEADS 6
#define HD 32
#define BATCH 256
#define NWIN 64
#define QSCALE 0.17677669529663687f  /* 32^-0.5 */

#define M_ROWS (BATCH * N_TOK)        /* 87808 = 1372*64 */
#define SMEM_ATTN (2 * 344 * 32 * 4)  /* K + V tiles, padded to 344 rows */

// ---------------- scratch (device globals: no allocations allowed) ----------
__device__ float g_q[BATCH * HEADS * N_TOK * HD];     // [b,h,n,d]
__device__ float g_k[BATCH * HEADS * N_TOK * HD];
__device__ float g_v[BATCH * HEADS * N_TOK * HD];
__device__ float g_ctx[BATCH * N_TOK * EMBED];        // [b,n,c]
__device__ float g_bias_t[HEADS * N_TOK * N_TOK];     // [h,k,q]  (transposed!)
__device__ float g_mask_t[NWIN * N_TOK * N_TOK];      // [w,k,q]  (transposed!)

// ------- bias gather (transposed): bias_t[h,k,q] = table[rel_idx[q,k], h] ---
__global__ void bias_gather_kernel(const float* __restrict__ table,
                                   const int* __restrict__ rel) {
    int i = blockIdx.x * blockDim.x + threadIdx.x;   // i = k*N + q
    if (i >= N_TOK * N_TOK) return;
    int q = i % N_TOK;
    int k = i / N_TOK;
    int r = rel[q * N_TOK + k];
#pragma unroll
    for (int h = 0; h < HEADS; ++h)
        g_bias_t[h * N_TOK * N_TOK + i] = table[r * HEADS + h];
}

// ------- mask transpose: mask_t[w,k,q] = mask[w,q,k] ------------------------
__global__ void mask_T_kernel(const float* __restrict__ mask) {
    int idx = blockIdx.x * blockDim.x + threadIdx.x;  // idx = (w*N + k)*N + q
    if (idx >= NWIN * N_TOK * N_TOK) return;
    int q = idx % N_TOK;
    int t = idx / N_TOK;
    int k = t % N_TOK;
    int w = t / N_TOK;
    g_mask_t[idx] = mask[((size_t)w * N_TOK + q) * N_TOK + k];
}

// ---------------- shared GEMM core: C[m,n] = sum_k A[m,k]*W[n,k] ------------
// BM=BN=64, BK=32, 256 threads, 4x4 per thread. K=192 (6 chunks), exact tiles.
__device__ __forceinline__ void gemm_core(const float* __restrict__ A,
                                          const float* __restrict__ W,
                                          int m0, int n0, int tid,
                                          float* As, float* Bs,
                                          float acc[4][4]) {
    const int tx = tid & 15, ty = tid >> 4;
#pragma unroll 1
    for (int kt = 0; kt < 6; ++kt) {
        const int k0 = kt * 32;
#pragma unroll
        for (int r = 0; r < 2; ++r) {
            int idx = tid + 256 * r;
            int row = idx >> 3, c4 = idx & 7;
            float4 av = *(const float4*)(A + (size_t)(m0 + row) * EMBED + k0 + c4 * 4);
            float4 wv = *(const float4*)(W + (size_t)(n0 + row) * EMBED + k0 + c4 * 4);
            int kb = c4 * 4;
            As[(kb + 0) * 68 + row] = av.x;
            As[(kb + 1) * 68 + row] = av.y;
            As[(kb + 2) * 68 + row] = av.z;
            As[(kb + 3) * 68 + row] = av.w;
            Bs[(kb + 0) * 68 + row] = wv.x;
            Bs[(kb + 1) * 68 + row] = wv.y;
            Bs[(kb + 2) * 68 + row] = wv.z;
            Bs[(kb + 3) * 68 + row] = wv.w;
        }
        __syncthreads();
#pragma unroll
        for (int kk = 0; kk < 32; ++kk) {
            float4 a4 = *(const float4*)(As + kk * 68 + ty * 4);
            float4 b4 = *(const float4*)(Bs + kk * 68 + tx * 4);
            float a[4] = {a4.x, a4.y, a4.z, a4.w};
            float b[4] = {b4.x, b4.y, b4.z, b4.w};
#pragma unroll
            for (int i = 0; i < 4; ++i)
#pragma unroll
                for (int j = 0; j < 4; ++j)
                    acc[i][j] += a[i] * b[j];
        }
        __syncthreads();
    }
}

// ---------------- fused Q + KV projections ----------------------------------
__global__ __launch_bounds__(256) void gemm_qkv_kernel(
    const float* __restrict__ x_in, const float* __restrict__ x_cross,
    const float* __restrict__ q_w, const float* __restrict__ kv_w) {
    __shared__ float As[32 * 68];
    __shared__ float Bs[32 * 68];
    const int tid = threadIdx.x;
    const int m0 = blockIdx.x * 64;
    const int yt = blockIdx.y;
    const bool isq = (yt < 3);
    const float* A = isq ? x_in : x_cross;
    const float* W = isq ? q_w : kv_w;
    const int n0 = isq ? yt * 64 : (yt - 3) * 64;

    float acc[4][4];
#pragma unroll
    for (int i = 0; i < 4; ++i)
#pragma unroll
        for (int j = 0; j < 4; ++j) acc[i][j] = 0.f;

    gemm_core(A, W, m0, n0, tid, As, Bs, acc);

    const int tx = tid & 15, ty = tid >> 4;
#pragma unroll
    for (int i = 0; i < 4; ++i) {
        int m = m0 + ty * 4 + i;
        int bb = m / N_TOK;
        int nn = m - bb * N_TOK;
#pragma unroll
        for (int j = 0; j < 4; ++j) {
            int n = n0 + tx * 4 + j;
            float v = acc[i][j];
            if (isq) {
                int h = n >> 5, d = n & 31;
                g_q[((size_t)(bb * HEADS + h) * N_TOK + nn) * HD + d] = v * QSCALE;
            } else {
                int nc = (n < EMBED) ? n : n - EMBED;
                float* dst = (n < EMBED) ? g_k : g_v;
                int h = nc >> 5, d = nc & 31;
                dst[((size_t)(bb * HEADS + h) * N_TOK + nn) * HD + d] = v;
            }
        }
    }
}

// ---------------- output projection: out = ctx @ proj_w^T + proj_b ---------
__global__ __launch_bounds__(256) void gemm_proj_kernel(
    const float* __restrict__ proj_w, const float* __restrict__ proj_b,
    float* __restrict__ out) {
    __shared__ float As[32 * 68];
    __shared__ float Bs[32 * 68];
    const int tid = threadIdx.x;
    const int m0 = blockIdx.x * 64;
    const int n0 = blockIdx.y * 64;

    float acc[4][4];
#pragma unroll
    for (int i = 0; i < 4; ++i)
#pragma unroll
        for (int j = 0; j < 4; ++j) acc[i][j] = 0.f;

    gemm_core(g_ctx, proj_w, m0, n0, tid, As, Bs, acc);

    const int tx = tid & 15, ty = tid >> 4;
#pragma unroll
    for (int i = 0; i < 4; ++i) {
        int m = m0 + ty * 4 + i;
#pragma unroll
        for (int j = 0; j < 4; ++j) {
            int n = n0 + tx * 4 + j;
            out[(size_t)m * EMBED + n] = acc[i][j] + proj_b[n];
        }
    }
}

// ---------------- flash attention per (b, h) --------------------------------
// 352 threads; one thread per q-row; K,V [344x32] in dynamic smem (row 343=0).
// Bias/mask read from transposed layouts -> coalesced (1 wavefront per LDG).
__global__ __launch_bounds__(352, 2) void attn_kernel() {
    extern __shared__ float sm[];
    float* Ks = sm;             // 344*32
    float* Vs = sm + 344 * 32;  // 344*32
    const int bh = blockIdx.x;
    const int b = bh / HEADS;
    const int h = bh - b * HEADS;
    const int w = b & (NWIN - 1);
    const int tid = threadIdx.x;

    const float4* Ksrc = (const float4*)(g_k + (size_t)bh * N_TOK * HD);
    const float4* Vsrc = (const float4*)(g_v + (size_t)bh * N_TOK * HD);
    float4* Kd = (float4*)Ks;
    float4* Vd = (float4*)Vs;
    const float4 z4 = make_float4(0.f, 0.f, 0.f, 0.f);
    for (int i = tid; i < 344 * 8; i += 352) {
        Kd[i] = (i < N_TOK * 8) ? Ksrc[i] : z4;
        Vd[i] = (i < N_TOK * 8) ? Vsrc[i] : z4;
    }
    __syncthreads();

    const int q = tid;
    if (q < N_TOK) {
        float4 qv[8];
        const float4* qsrc = (const float4*)(g_q + ((size_t)bh * N_TOK + q) * HD);
#pragma unroll
        for (int c = 0; c < 8; ++c) qv[c] = qsrc[c];

        // column pointers: advance by N_TOK per k; lanes (q) contiguous.
        const float* bcol = g_bias_t + (size_t)h * N_TOK * N_TOK + q;
        const float* mcol = g_mask_t + (size_t)w * N_TOK * N_TOK + q;

        float mrun = -1e30f, l = 0.f;
        float4 accv[8];
#pragma unroll
        for (int c = 0; c < 8; ++c) accv[c] = z4;

#pragma unroll 1
        for (int k0 = 0; k0 < N_TOK; k0 += 8) {
            float s[8];
#pragma unroll
            for (int j = 0; j < 8; ++j) {
                int k = k0 + j;
                float sj = 0.f;
#pragma unroll
                for (int c = 0; c < 8; ++c) {
                    float4 kv = Kd[k * 8 + c];
                    sj += qv[c].x * kv.x + qv[c].y * kv.y +
                          qv[c].z * kv.z + qv[c].w * kv.w;
                }
                if (k < N_TOK)
                    s[j] = sj + bcol[(size_t)k * N_TOK] + mcol[(size_t)k * N_TOK];
                else
                    s[j] = -1e30f;
            }
            float mc = s[0];
#pragma unroll
            for (int j = 1; j < 8; ++j) mc = fmaxf(mc, s[j]);
            float newm = fmaxf(mrun, mc);
            float alpha = __expf(mrun - newm);
            l *= alpha;
#pragma unroll
            for (int c = 0; c < 8; ++c) {
                accv[c].x *= alpha; accv[c].y *= alpha;
                accv[c].z *= alpha; accv[c].w *= alpha;
            }
#pragma unroll
            for (int j = 0; j < 8; ++j) {
                float p = __expf(s[j] - newm);
                l += p;
#pragma unroll
                for (int c = 0; c < 8; ++c) {
                    float4 vv = Vd[(k0 + j) * 8 + c];
                    accv[c].x += p * vv.x; accv[c].y += p * vv.y;
                    accv[c].z += p * vv.z; accv[c].w += p * vv.w;
                }
            }
            mrun = newm;
        }

        float inv = __fdividef(1.f, l);
        float4* dst = (float4*)(g_ctx + ((size_t)(b * N_TOK + q)) * EMBED + h * HD);
#pragma unroll
        for (int c = 0; c < 8; ++c) {
            float4 o = accv[c];
            o.x *= inv; o.y *= inv; o.z *= inv; o.w *= inv;
            dst[c] = o;
        }
    }
}

// ---------------- launch -----------------------------------------------------
extern "C" void kernel_launch(void* const* d_in, const int* in_sizes, int n_in,
                              void* d_out, int out_size) {
    const float* x_in    = (const float*)d_in[0];
    const float* x_cross = (const float*)d_in[1];
    const float* mask    = (const float*)d_in[2];
    const float* q_w     = (const float*)d_in[3];
    const float* kv_w    = (const float*)d_in[4];
    const float* proj_w  = (const float*)d_in[5];
    const float* proj_b  = (const float*)d_in[6];
    const float* table   = (const float*)d_in[7];
    const int*   rel     = (const int*)d_in[8];
    float* out = (float*)d_out;

    cudaFuncSetAttribute(attn_kernel,
                         cudaFuncAttributeMaxDynamicSharedMemorySize, SMEM_ATTN);

    bias_gather_kernel<<<(N_TOK * N_TOK + 255) / 256, 256>>>(table, rel);
    mask_T_kernel<<<(NWIN * N_TOK * N_TOK + 255) / 256, 256>>>(mask);
    gemm_qkv_kernel<<<dim3(M_ROWS / 64, 9), 256>>>(x_in, x_cross, q_w, kv_w);
    attn_kernel<<<BATCH * HEADS, 352, SMEM_ATTN>>>();
    gemm_proj_kernel<<<dim3(M_ROWS / 64, 3), 256>>>(proj_w, proj_b, out);
}

// round 5
// speedup vs baseline: 1.5647x; 1.2892x over previous
#include <cuda_runtime.h>
#include <cstdint>

#define N_TOK 343
#define EMBED 192
#define HEADS 6
#define HD 32
#define BATCH 256
#define NWIN 64
#define QSCALE 0.17677669529663687f  /* 32^-0.5 */

#define M_ROWS (BATCH * N_TOK)        /* 87808 = 1372*64 */
#define SMEM_ATTN (2 * 344 * 32 * 4)  /* K + V tiles, padded to 344 rows */

/* ---------------- scratch (device globals) ------------------------------- */
__device__ float g_q[BATCH * HEADS * N_TOK * HD];     // [b,h,n,d]
__device__ float g_k[BATCH * HEADS * N_TOK * HD];
__device__ float g_v[BATCH * HEADS * N_TOK * HD];
__device__ float g_ctx[BATCH * N_TOK * EMBED];        // [b,n,c]
__device__ float g_bias_t[HEADS * N_TOK * N_TOK];     // [h,k,q]
__device__ float g_mask_t[NWIN * N_TOK * N_TOK];      // [w,k,q]

/* ---------------- helpers ------------------------------------------------- */
__device__ __forceinline__ uint32_t f2tf(float f) {
    uint32_t r;
    asm("cvt.rna.tf32.f32 %0, %1;" : "=r"(r) : "f"(f));
    return r;
}
__device__ __forceinline__ void mma_tf32(float c[4],
                                         uint32_t a0, uint32_t a1,
                                         uint32_t a2, uint32_t a3,
                                         uint32_t b0, uint32_t b1) {
    asm volatile(
        "mma.sync.aligned.m16n8k8.row.col.f32.tf32.tf32.f32 "
        "{%0,%1,%2,%3}, {%4,%5,%6,%7}, {%8,%9}, {%0,%1,%2,%3};"
        : "+f"(c[0]), "+f"(c[1]), "+f"(c[2]), "+f"(c[3])
        : "r"(a0), "r"(a1), "r"(a2), "r"(a3), "r"(b0), "r"(b1));
}

/* ---------------- bias gather / mask transpose --------------------------- */
__global__ void bias_gather_kernel(const float* __restrict__ table,
                                   const int* __restrict__ rel) {
    int i = blockIdx.x * blockDim.x + threadIdx.x;   // i = k*N + q
    if (i >= N_TOK * N_TOK) return;
    int q = i % N_TOK;
    int k = i / N_TOK;
    int r = rel[q * N_TOK + k];
#pragma unroll
    for (int h = 0; h < HEADS; ++h)
        g_bias_t[h * N_TOK * N_TOK + i] = table[r * HEADS + h];
}

__global__ void mask_T_kernel(const float* __restrict__ mask) {
    int idx = blockIdx.x * blockDim.x + threadIdx.x;
    if (idx >= NWIN * N_TOK * N_TOK) return;
    int q = idx % N_TOK;
    int t = idx / N_TOK;
    int k = t % N_TOK;
    int w = t / N_TOK;
    g_mask_t[idx] = mask[((size_t)w * N_TOK + q) * N_TOK + k];
}

/* ------- warp-MMA tf32 GEMM core: C[64x64] = A[64x192] * W[64x192]^T -----
   8 warps (2m x 4n), warp tile 32x16, mma m16n8k8.
   As/Bs layout [row][k] stride 36 (conflict-free fragment loads).
   Result left in Stage[64][65].                                            */
__device__ __forceinline__ void mma_gemm_tile(const float* __restrict__ A,
                                              const float* __restrict__ W,
                                              int m0, int n0,
                                              float* As, float* Bs,
                                              float* Stage) {
    const int tid = threadIdx.x;
    const int lane = tid & 31, warp = tid >> 5;
    const int wm = warp & 1, wn = warp >> 1;
    const int g = lane >> 2, t = lane & 3;
    const uint32_t* Au = (const uint32_t*)As;
    const uint32_t* Bu = (const uint32_t*)Bs;

    float c[2][2][4];
#pragma unroll
    for (int mi = 0; mi < 2; ++mi)
#pragma unroll
        for (int ni = 0; ni < 2; ++ni)
#pragma unroll
            for (int e = 0; e < 4; ++e) c[mi][ni][e] = 0.f;

#pragma unroll 1
    for (int kt = 0; kt < 6; ++kt) {
        const int k0 = kt * 32;
#pragma unroll
        for (int r = 0; r < 2; ++r) {
            int idx = tid + 256 * r;
            int row = idx >> 3, kq = idx & 7;
            float4 av = *(const float4*)(A + (size_t)(m0 + row) * EMBED + k0 + kq * 4);
            float4 wv = *(const float4*)(W + (size_t)(n0 + row) * EMBED + k0 + kq * 4);
            uint4 ta, tb;
            ta.x = f2tf(av.x); ta.y = f2tf(av.y); ta.z = f2tf(av.z); ta.w = f2tf(av.w);
            tb.x = f2tf(wv.x); tb.y = f2tf(wv.y); tb.z = f2tf(wv.z); tb.w = f2tf(wv.w);
            *(uint4*)(As + row * 36 + kq * 4) = ta;
            *(uint4*)(Bs + row * 36 + kq * 4) = tb;
        }
        __syncthreads();
#pragma unroll
        for (int ks = 0; ks < 4; ++ks) {
            const int k = ks * 8;
            uint32_t a[2][4], b[2][2];
#pragma unroll
            for (int mi = 0; mi < 2; ++mi) {
                int mb = wm * 32 + mi * 16;
                a[mi][0] = Au[(mb + g) * 36 + k + t];
                a[mi][1] = Au[(mb + 8 + g) * 36 + k + t];
                a[mi][2] = Au[(mb + g) * 36 + k + 4 + t];
                a[mi][3] = Au[(mb + 8 + g) * 36 + k + 4 + t];
            }
#pragma unroll
            for (int ni = 0; ni < 2; ++ni) {
                int nb = wn * 16 + ni * 8;
                b[ni][0] = Bu[(nb + g) * 36 + k + t];
                b[ni][1] = Bu[(nb + g) * 36 + k + 4 + t];
            }
#pragma unroll
            for (int mi = 0; mi < 2; ++mi)
#pragma unroll
                for (int ni = 0; ni < 2; ++ni)
                    mma_tf32(c[mi][ni], a[mi][0], a[mi][1], a[mi][2], a[mi][3],
                             b[ni][0], b[ni][1]);
        }
        __syncthreads();
    }

    /* fragments -> stage */
#pragma unroll
    for (int mi = 0; mi < 2; ++mi)
#pragma unroll
        for (int ni = 0; ni < 2; ++ni) {
            int row = wm * 32 + mi * 16 + g;
            int col = wn * 16 + ni * 8 + 2 * t;
            Stage[row * 65 + col]       = c[mi][ni][0];
            Stage[row * 65 + col + 1]   = c[mi][ni][1];
            Stage[(row + 8) * 65 + col]     = c[mi][ni][2];
            Stage[(row + 8) * 65 + col + 1] = c[mi][ni][3];
        }
    __syncthreads();
}

/* ---------------- fused Q + KV projections (tensor-core) ----------------- */
__global__ __launch_bounds__(256) void gemm_qkv_kernel(
    const float* __restrict__ x_in, const float* __restrict__ x_cross,
    const float* __restrict__ q_w, const float* __restrict__ kv_w) {
    __shared__ float As[64 * 36];
    __shared__ float Bs[64 * 36];
    __shared__ float Stage[64 * 65];
    const int tid = threadIdx.x;
    const int m0 = blockIdx.x * 64;
    const int yt = blockIdx.y;
    const bool isq = (yt < 3);
    const float* A = isq ? x_in : x_cross;
    const float* W = isq ? q_w : kv_w;
    const int n0 = isq ? yt * 64 : (yt - 3) * 64;

    mma_gemm_tile(A, W, m0, n0, As, Bs, Stage);

#pragma unroll 4
    for (int j = 0; j < 16; ++j) {
        int i = tid + 256 * j;
        int ml = i >> 6, cc = i & 63;
        float v = Stage[ml * 65 + cc];
        int m = m0 + ml;
        int bb = m / N_TOK;
        int nn = m - bb * N_TOK;
        int n = n0 + cc;
        if (isq) {
            int h = n >> 5, d = n & 31;
            g_q[((size_t)(bb * HEADS + h) * N_TOK + nn) * HD + d] = v * QSCALE;
        } else {
            int nc = (n < EMBED) ? n : n - EMBED;
            float* dst = (n < EMBED) ? g_k : g_v;
            int h = nc >> 5, d = nc & 31;
            dst[((size_t)(bb * HEADS + h) * N_TOK + nn) * HD + d] = v;
        }
    }
}

/* ---------------- output projection (tensor-core) ------------------------ */
__global__ __launch_bounds__(256) void gemm_proj_kernel(
    const float* __restrict__ proj_w, const float* __restrict__ proj_b,
    float* __restrict__ out) {
    __shared__ float As[64 * 36];
    __shared__ float Bs[64 * 36];
    __shared__ float Stage[64 * 65];
    const int tid = threadIdx.x;
    const int m0 = blockIdx.x * 64;
    const int n0 = blockIdx.y * 64;

    mma_gemm_tile(g_ctx, proj_w, m0, n0, As, Bs, Stage);

#pragma unroll 4
    for (int j = 0; j < 16; ++j) {
        int i = tid + 256 * j;
        int ml = i >> 6, cc = i & 63;
        int m = m0 + ml;
        int n = n0 + cc;
        out[(size_t)m * EMBED + n] = Stage[ml * 65 + cc] + proj_b[n];
    }
}

/* ---------------- flash attention per (b, h) — fp32 (proven) ------------- */
__global__ __launch_bounds__(352, 2) void attn_kernel() {
    extern __shared__ float sm[];
    float* Ks = sm;
    float* Vs = sm + 344 * 32;
    const int bh = blockIdx.x;
    const int b = bh / HEADS;
    const int h = bh - b * HEADS;
    const int w = b & (NWIN - 1);
    const int tid = threadIdx.x;

    const float4* Ksrc = (const float4*)(g_k + (size_t)bh * N_TOK * HD);
    const float4* Vsrc = (const float4*)(g_v + (size_t)bh * N_TOK * HD);
    float4* Kd = (float4*)Ks;
    float4* Vd = (float4*)Vs;
    const float4 z4 = make_float4(0.f, 0.f, 0.f, 0.f);
    for (int i = tid; i < 344 * 8; i += 352) {
        Kd[i] = (i < N_TOK * 8) ? Ksrc[i] : z4;
        Vd[i] = (i < N_TOK * 8) ? Vsrc[i] : z4;
    }
    __syncthreads();

    const int q = tid;
    if (q < N_TOK) {
        float4 qv[8];
        const float4* qsrc = (const float4*)(g_q + ((size_t)bh * N_TOK + q) * HD);
#pragma unroll
        for (int c = 0; c < 8; ++c) qv[c] = qsrc[c];

        const float* bcol = g_bias_t + (size_t)h * N_TOK * N_TOK + q;
        const float* mcol = g_mask_t + (size_t)w * N_TOK * N_TOK + q;

        float mrun = -1e30f, l = 0.f;
        float4 accv[8];
#pragma unroll
        for (int c = 0; c < 8; ++c) accv[c] = z4;

#pragma unroll 1
        for (int k0 = 0; k0 < N_TOK; k0 += 8) {
            float s[8];
#pragma unroll
            for (int j = 0; j < 8; ++j) {
                int k = k0 + j;
                float sj = 0.f;
#pragma unroll
                for (int c = 0; c < 8; ++c) {
                    float4 kv = Kd[k * 8 + c];
                    sj += qv[c].x * kv.x + qv[c].y * kv.y +
                          qv[c].z * kv.z + qv[c].w * kv.w;
                }
                if (k < N_TOK)
                    s[j] = sj + bcol[(size_t)k * N_TOK] + mcol[(size_t)k * N_TOK];
                else
                    s[j] = -1e30f;
            }
            float mc = s[0];
#pragma unroll
            for (int j = 1; j < 8; ++j) mc = fmaxf(mc, s[j]);
            float newm = fmaxf(mrun, mc);
            float alpha = __expf(mrun - newm);
            l *= alpha;
#pragma unroll
            for (int c = 0; c < 8; ++c) {
                accv[c].x *= alpha; accv[c].y *= alpha;
                accv[c].z *= alpha; accv[c].w *= alpha;
            }
#pragma unroll
            for (int j = 0; j < 8; ++j) {
                float p = __expf(s[j] - newm);
                l += p;
#pragma unroll
                for (int c = 0; c < 8; ++c) {
                    float4 vv = Vd[(k0 + j) * 8 + c];
                    accv[c].x += p * vv.x; accv[c].y += p * vv.y;
                    accv[c].z += p * vv.z; accv[c].w += p * vv.w;
                }
            }
            mrun = newm;
        }

        float inv = __fdividef(1.f, l);
        float4* dst = (float4*)(g_ctx + ((size_t)(b * N_TOK + q)) * EMBED + h * HD);
#pragma unroll
        for (int c = 0; c < 8; ++c) {
            float4 o = accv[c];
            o.x *= inv; o.y *= inv; o.z *= inv; o.w *= inv;
            dst[c] = o;
        }
    }
}

/* ---------------- launch -------------------------------------------------- */
extern "C" void kernel_launch(void* const* d_in, const int* in_sizes, int n_in,
                              void* d_out, int out_size) {
    const float* x_in    = (const float*)d_in[0];
    const float* x_cross = (const float*)d_in[1];
    const float* mask    = (const float*)d_in[2];
    const float* q_w     = (const float*)d_in[3];
    const float* kv_w    = (const float*)d_in[4];
    const float* proj_w  = (const float*)d_in[5];
    const float* proj_b  = (const float*)d_in[6];
    const float* table   = (const float*)d_in[7];
    const int*   rel     = (const int*)d_in[8];
    float* out = (float*)d_out;

    cudaFuncSetAttribute(attn_kernel,
                         cudaFuncAttributeMaxDynamicSharedMemorySize, SMEM_ATTN);

    bias_gather_kernel<<<(N_TOK * N_TOK + 255) / 256, 256>>>(table, rel);
    mask_T_kernel<<<(NWIN * N_TOK * N_TOK + 255) / 256, 256>>>(mask);
    gemm_qkv_kernel<<<dim3(M_ROWS / 64, 9), 256>>>(x_in, x_cross, q_w, kv_w);
    attn_kernel<<<BATCH * HEADS, 352, SMEM_ATTN>>>();
    gemm_proj_kernel<<<dim3(M_ROWS / 64, 3), 256>>>(proj_w, proj_b, out);
}

// round 6
// speedup vs baseline: 2.0585x; 1.3155x over previous
#include <cuda_runtime.h>
#include <cstdint>

#define N_TOK 343
#define EMBED 192
#define HEADS 6
#define HD 32
#define BATCH 256
#define NWIN 64
#define QSCALE 0.17677669529663687f  /* 32^-0.5 */

#define M_ROWS (BATCH * N_TOK)        /* 87808 = 1372*64 */
#define NKT 6                          /* 384 = 6*64 k tiles */
#define NQT 6                          /* 6 q tiles */

/* ---------------- scratch (device globals) ------------------------------- */
__device__ float g_q[BATCH * HEADS * N_TOK * HD];     // [b,h,n,d] (scaled)
__device__ float g_k[BATCH * HEADS * N_TOK * HD];
__device__ float g_v[BATCH * HEADS * N_TOK * HD];
__device__ float g_ctx[BATCH * N_TOK * EMBED];        // [b,n,c]
__device__ float g_bias_t[HEADS * N_TOK * N_TOK];     // [h,k,q]
__device__ float g_mask_t[NWIN * N_TOK * N_TOK];      // [w,k,q]

/* ---------------- helpers ------------------------------------------------- */
__device__ __forceinline__ uint32_t f2tf(float f) {
    uint32_t r;
    asm("cvt.rna.tf32.f32 %0, %1;" : "=r"(r) : "f"(f));
    return r;
}
__device__ __forceinline__ void mma_tf32(float c[4],
                                         uint32_t a0, uint32_t a1,
                                         uint32_t a2, uint32_t a3,
                                         uint32_t b0, uint32_t b1) {
    asm volatile(
        "mma.sync.aligned.m16n8k8.row.col.f32.tf32.tf32.f32 "
        "{%0,%1,%2,%3}, {%4,%5,%6,%7}, {%8,%9}, {%0,%1,%2,%3};"
        : "+f"(c[0]), "+f"(c[1]), "+f"(c[2]), "+f"(c[3])
        : "r"(a0), "r"(a1), "r"(a2), "r"(a3), "r"(b0), "r"(b1));
}

/* ---------------- bias gather / mask transpose --------------------------- */
__global__ void bias_gather_kernel(const float* __restrict__ table,
                                   const int* __restrict__ rel) {
    int i = blockIdx.x * blockDim.x + threadIdx.x;   // i = k*N + q
    if (i >= N_TOK * N_TOK) return;
    int q = i % N_TOK;
    int k = i / N_TOK;
    int r = rel[q * N_TOK + k];
#pragma unroll
    for (int h = 0; h < HEADS; ++h)
        g_bias_t[h * N_TOK * N_TOK + i] = table[r * HEADS + h];
}

__global__ void mask_T_kernel(const float* __restrict__ mask) {
    int idx = blockIdx.x * blockDim.x + threadIdx.x;
    if (idx >= NWIN * N_TOK * N_TOK) return;
    int q = idx % N_TOK;
    int t = idx / N_TOK;
    int k = t % N_TOK;
    int w = t / N_TOK;
    g_mask_t[idx] = mask[((size_t)w * N_TOK + q) * N_TOK + k];
}

/* ------- warp-MMA tf32 GEMM core (validated round 5) --------------------- */
__device__ __forceinline__ void mma_gemm_tile(const float* __restrict__ A,
                                              const float* __restrict__ W,
                                              int m0, int n0,
                                              float* As, float* Bs,
                                              float* Stage) {
    const int tid = threadIdx.x;
    const int lane = tid & 31, warp = tid >> 5;
    const int wm = warp & 1, wn = warp >> 1;
    const int g = lane >> 2, t = lane & 3;
    const uint32_t* Au = (const uint32_t*)As;
    const uint32_t* Bu = (const uint32_t*)Bs;

    float c[2][2][4];
#pragma unroll
    for (int mi = 0; mi < 2; ++mi)
#pragma unroll
        for (int ni = 0; ni < 2; ++ni)
#pragma unroll
            for (int e = 0; e < 4; ++e) c[mi][ni][e] = 0.f;

#pragma unroll 1
    for (int kt = 0; kt < 6; ++kt) {
        const int k0 = kt * 32;
#pragma unroll
        for (int r = 0; r < 2; ++r) {
            int idx = tid + 256 * r;
            int row = idx >> 3, kq = idx & 7;
            float4 av = *(const float4*)(A + (size_t)(m0 + row) * EMBED + k0 + kq * 4);
            float4 wv = *(const float4*)(W + (size_t)(n0 + row) * EMBED + k0 + kq * 4);
            uint4 ta, tb;
            ta.x = f2tf(av.x); ta.y = f2tf(av.y); ta.z = f2tf(av.z); ta.w = f2tf(av.w);
            tb.x = f2tf(wv.x); tb.y = f2tf(wv.y); tb.z = f2tf(wv.z); tb.w = f2tf(wv.w);
            *(uint4*)(As + row * 36 + kq * 4) = ta;
            *(uint4*)(Bs + row * 36 + kq * 4) = tb;
        }
        __syncthreads();
#pragma unroll
        for (int ks = 0; ks < 4; ++ks) {
            const int k = ks * 8;
            uint32_t a[2][4], b[2][2];
#pragma unroll
            for (int mi = 0; mi < 2; ++mi) {
                int mb = wm * 32 + mi * 16;
                a[mi][0] = Au[(mb + g) * 36 + k + t];
                a[mi][1] = Au[(mb + 8 + g) * 36 + k + t];
                a[mi][2] = Au[(mb + g) * 36 + k + 4 + t];
                a[mi][3] = Au[(mb + 8 + g) * 36 + k + 4 + t];
            }
#pragma unroll
            for (int ni = 0; ni < 2; ++ni) {
                int nb = wn * 16 + ni * 8;
                b[ni][0] = Bu[(nb + g) * 36 + k + t];
                b[ni][1] = Bu[(nb + g) * 36 + k + 4 + t];
            }
#pragma unroll
            for (int mi = 0; mi < 2; ++mi)
#pragma unroll
                for (int ni = 0; ni < 2; ++ni)
                    mma_tf32(c[mi][ni], a[mi][0], a[mi][1], a[mi][2], a[mi][3],
                             b[ni][0], b[ni][1]);
        }
        __syncthreads();
    }

#pragma unroll
    for (int mi = 0; mi < 2; ++mi)
#pragma unroll
        for (int ni = 0; ni < 2; ++ni) {
            int row = wm * 32 + mi * 16 + g;
            int col = wn * 16 + ni * 8 + 2 * t;
            Stage[row * 65 + col]       = c[mi][ni][0];
            Stage[row * 65 + col + 1]   = c[mi][ni][1];
            Stage[(row + 8) * 65 + col]     = c[mi][ni][2];
            Stage[(row + 8) * 65 + col + 1] = c[mi][ni][3];
        }
    __syncthreads();
}

/* ---------------- fused Q + KV projections (tensor-core) ----------------- */
__global__ __launch_bounds__(256) void gemm_qkv_kernel(
    const float* __restrict__ x_in, const float* __restrict__ x_cross,
    const float* __restrict__ q_w, const float* __restrict__ kv_w) {
    __shared__ float As[64 * 36];
    __shared__ float Bs[64 * 36];
    __shared__ float Stage[64 * 65];
    const int tid = threadIdx.x;
    const int m0 = blockIdx.x * 64;
    const int yt = blockIdx.y;
    const bool isq = (yt < 3);
    const float* A = isq ? x_in : x_cross;
    const float* W = isq ? q_w : kv_w;
    const int n0 = isq ? yt * 64 : (yt - 3) * 64;

    mma_gemm_tile(A, W, m0, n0, As, Bs, Stage);

#pragma unroll 4
    for (int j = 0; j < 16; ++j) {
        int i = tid + 256 * j;
        int ml = i >> 6, cc = i & 63;
        float v = Stage[ml * 65 + cc];
        int m = m0 + ml;
        int bb = m / N_TOK;
        int nn = m - bb * N_TOK;
        int n = n0 + cc;
        if (isq) {
            int h = n >> 5, d = n & 31;
            g_q[((size_t)(bb * HEADS + h) * N_TOK + nn) * HD + d] = v * QSCALE;
        } else {
            int nc = (n < EMBED) ? n : n - EMBED;
            float* dst = (n < EMBED) ? g_k : g_v;
            int h = nc >> 5, d = nc & 31;
            dst[((size_t)(bb * HEADS + h) * N_TOK + nn) * HD + d] = v;
        }
    }
}

/* ---------------- output projection (tensor-core) ------------------------ */
__global__ __launch_bounds__(256) void gemm_proj_kernel(
    const float* __restrict__ proj_w, const float* __restrict__ proj_b,
    float* __restrict__ out) {
    __shared__ float As[64 * 36];
    __shared__ float Bs[64 * 36];
    __shared__ float Stage[64 * 65];
    const int tid = threadIdx.x;
    const int m0 = blockIdx.x * 64;
    const int n0 = blockIdx.y * 64;

    mma_gemm_tile(g_ctx, proj_w, m0, n0, As, Bs, Stage);

#pragma unroll 4
    for (int j = 0; j < 16; ++j) {
        int i = tid + 256 * j;
        int ml = i >> 6, cc = i & 63;
        int m = m0 + ml;
        int n = n0 + cc;
        out[(size_t)m * EMBED + n] = Stage[ml * 65 + cc] + proj_b[n];
    }
}

/* ---------------- tensor-core flash attention -----------------------------
   One CTA per (b, h, q-tile of 64). 256 threads = 8 warps.
   S tile 64x64 via mma tf32 (warps 2m x 4n), stored Stage[k][q] stride 68.
   Online softmax (4 thr/row), then O += P*V via mma (warps 2m x 4n over
   64x32, warp n-tile 8). V transposed in smem Vs[d][token].               */
__global__ __launch_bounds__(256, 2) void attn_mma_kernel() {
    __shared__ uint32_t Qs[64 * 36];
    __shared__ uint32_t Ks[64 * 36];
    __shared__ uint32_t Vs[32 * 68];
    __shared__ float Stage[64 * 68];      /* [k][q] */
    __shared__ float s_m[64], s_l[64], s_alpha[64];

    const int bid = blockIdx.x;
    const int qt = bid % NQT;
    const int bh = bid / NQT;
    const int b  = bh / HEADS;
    const int h  = bh - b * HEADS;
    const int w  = b & (NWIN - 1);
    const int q0 = qt * 64;

    const int tid = threadIdx.x;
    const int lane = tid & 31, warp = tid >> 5;
    const int g = lane >> 2, t = lane & 3;
    const int wm = warp & 1, wn = warp >> 1;

    const float* Qg = g_q + (size_t)bh * N_TOK * HD;
    const float* Kg = g_k + (size_t)bh * N_TOK * HD;
    const float* Vg = g_v + (size_t)bh * N_TOK * HD;
    const float* biasp = g_bias_t + (size_t)h * N_TOK * N_TOK;
    const float* maskp = g_mask_t + (size_t)w * N_TOK * N_TOK;

    /* Q tile -> Qs[row][36] tf32 (rows >= N_TOK zeroed) */
#pragma unroll
    for (int r = 0; r < 2; ++r) {
        int idx = tid + 256 * r;
        int row = idx >> 3, c4 = idx & 7;
        int qg = q0 + row;
        float4 v = (qg < N_TOK) ? *(const float4*)(Qg + (size_t)qg * HD + c4 * 4)
                                : make_float4(0.f, 0.f, 0.f, 0.f);
        uint4 tv;
        tv.x = f2tf(v.x); tv.y = f2tf(v.y); tv.z = f2tf(v.z); tv.w = f2tf(v.w);
        *(uint4*)(Qs + row * 36 + c4 * 4) = tv;
    }
    if (tid < 64) { s_m[tid] = -1e30f; s_l[tid] = 0.f; }

    float o[2][4];
#pragma unroll
    for (int mi = 0; mi < 2; ++mi)
#pragma unroll
        for (int e = 0; e < 4; ++e) o[mi][e] = 0.f;

#pragma unroll 1
    for (int kt = 0; kt < NKT; ++kt) {
        const int k0 = kt * 64;
        __syncthreads();                  /* prev PV done; smem free */

        /* K tile -> Ks[token][36] tf32 ; V tile -> Vs[d][token] tf32 */
#pragma unroll
        for (int r = 0; r < 2; ++r) {
            int idx = tid + 256 * r;
            int row = idx >> 3, c4 = idx & 7;
            int kg = k0 + row;
            float4 kv = (kg < N_TOK) ? *(const float4*)(Kg + (size_t)kg * HD + c4 * 4)
                                     : make_float4(0.f, 0.f, 0.f, 0.f);
            uint4 tk;
            tk.x = f2tf(kv.x); tk.y = f2tf(kv.y); tk.z = f2tf(kv.z); tk.w = f2tf(kv.w);
            *(uint4*)(Ks + row * 36 + c4 * 4) = tk;

            float4 vv = (kg < N_TOK) ? *(const float4*)(Vg + (size_t)kg * HD + c4 * 4)
                                     : make_float4(0.f, 0.f, 0.f, 0.f);
            int d = c4 * 4;
            Vs[(d + 0) * 68 + row] = f2tf(vv.x);
            Vs[(d + 1) * 68 + row] = f2tf(vv.y);
            Vs[(d + 2) * 68 + row] = f2tf(vv.z);
            Vs[(d + 3) * 68 + row] = f2tf(vv.w);
        }
        __syncthreads();

        /* S = Q K^T : warps 2m x 4n, warp tile 32x16, K=32 (4 ksteps) */
        {
            float c[2][2][4];
#pragma unroll
            for (int mi = 0; mi < 2; ++mi)
#pragma unroll
                for (int ni = 0; ni < 2; ++ni)
#pragma unroll
                    for (int e = 0; e < 4; ++e) c[mi][ni][e] = 0.f;
#pragma unroll
            for (int ks = 0; ks < 4; ++ks) {
                const int k = ks * 8;
                uint32_t a[2][4], bf[2][2];
#pragma unroll
                for (int mi = 0; mi < 2; ++mi) {
                    int mb = wm * 32 + mi * 16;
                    a[mi][0] = Qs[(mb + g) * 36 + k + t];
                    a[mi][1] = Qs[(mb + 8 + g) * 36 + k + t];
                    a[mi][2] = Qs[(mb + g) * 36 + k + 4 + t];
                    a[mi][3] = Qs[(mb + 8 + g) * 36 + k + 4 + t];
                }
#pragma unroll
                for (int ni = 0; ni < 2; ++ni) {
                    int nb = wn * 16 + ni * 8;
                    bf[ni][0] = Ks[(nb + g) * 36 + k + t];
                    bf[ni][1] = Ks[(nb + g) * 36 + k + 4 + t];
                }
#pragma unroll
                for (int mi = 0; mi < 2; ++mi)
#pragma unroll
                    for (int ni = 0; ni < 2; ++ni)
                        mma_tf32(c[mi][ni], a[mi][0], a[mi][1], a[mi][2], a[mi][3],
                                 bf[ni][0], bf[ni][1]);
            }
            /* fragments -> Stage[k][q] (conflict-free) */
#pragma unroll
            for (int mi = 0; mi < 2; ++mi)
#pragma unroll
                for (int ni = 0; ni < 2; ++ni) {
                    int row = wm * 32 + mi * 16 + g;
                    int col = wn * 16 + ni * 8 + 2 * t;
                    Stage[col * 68 + row]           = c[mi][ni][0];
                    Stage[(col + 1) * 68 + row]     = c[mi][ni][1];
                    Stage[col * 68 + row + 8]       = c[mi][ni][2];
                    Stage[(col + 1) * 68 + row + 8] = c[mi][ni][3];
                }
        }
        __syncthreads();

        /* phase A: bias + mask + pad masking (coalesced in q) */
#pragma unroll
        for (int j = 0; j < 16; ++j) {
            int i = tid + 256 * j;
            int kk = i >> 6, qq = i & 63;
            int kg = k0 + kk, qg = q0 + qq;
            float* sp = &Stage[kk * 68 + qq];
            if (kg < N_TOK && qg < N_TOK)
                *sp += biasp[(size_t)kg * N_TOK + qg] + maskp[(size_t)kg * N_TOK + qg];
            else
                *sp = -1e30f;
        }
        __syncthreads();

        /* phase B: online row softmax; q = tid>>2, k = tq+4j */
        {
            const int q = tid >> 2, tq = tid & 3;
            float sv[16];
            float mx = -1e30f;
#pragma unroll
            for (int j = 0; j < 16; ++j) {
                sv[j] = Stage[(tq + 4 * j) * 68 + q];
                mx = fmaxf(mx, sv[j]);
            }
            mx = fmaxf(mx, __shfl_xor_sync(0xFFFFFFFFu, mx, 1));
            mx = fmaxf(mx, __shfl_xor_sync(0xFFFFFFFFu, mx, 2));
            float mold = s_m[q];
            float newm = fmaxf(mold, mx);
            float sum = 0.f;
#pragma unroll
            for (int j = 0; j < 16; ++j) {
                float p = __expf(sv[j] - newm);
                sum += p;
                Stage[(tq + 4 * j) * 68 + q] = p;
            }
            sum += __shfl_xor_sync(0xFFFFFFFFu, sum, 1);
            sum += __shfl_xor_sync(0xFFFFFFFFu, sum, 2);
            if (tq == 0) {
                float alpha = __expf(mold - newm);
                s_alpha[q] = alpha;
                s_l[q] = s_l[q] * alpha + sum;
                s_m[q] = newm;
            }
        }
        __syncthreads();

        /* PV: O = alpha*O + P @ V ; warps 2m x 4n over 64x32, K=64 */
        {
#pragma unroll
            for (int mi = 0; mi < 2; ++mi) {
                int r0 = wm * 32 + mi * 16 + g;
                float a0 = s_alpha[r0], a1 = s_alpha[r0 + 8];
                o[mi][0] *= a0; o[mi][1] *= a0;
                o[mi][2] *= a1; o[mi][3] *= a1;
            }
            const int nb = wn * 8;
#pragma unroll
            for (int ks = 0; ks < 8; ++ks) {
                const int k = ks * 8;
                uint32_t b0 = Vs[(nb + g) * 68 + k + t];
                uint32_t b1 = Vs[(nb + g) * 68 + k + 4 + t];
#pragma unroll
                for (int mi = 0; mi < 2; ++mi) {
                    int mb = wm * 32 + mi * 16;
                    uint32_t a0 = f2tf(Stage[(k + t) * 68 + mb + g]);
                    uint32_t a1 = f2tf(Stage[(k + t) * 68 + mb + 8 + g]);
                    uint32_t a2 = f2tf(Stage[(k + 4 + t) * 68 + mb + g]);
                    uint32_t a3 = f2tf(Stage[(k + 4 + t) * 68 + mb + 8 + g]);
                    mma_tf32(o[mi], a0, a1, a2, a3, b0, b1);
                }
            }
        }
    }
    __syncthreads();

    /* normalize + write O fragments to g_ctx */
#pragma unroll
    for (int mi = 0; mi < 2; ++mi) {
        int r0 = wm * 32 + mi * 16 + g;
        int col = wn * 8 + 2 * t;
#pragma unroll
        for (int hh = 0; hh < 2; ++hh) {
            int r = r0 + 8 * hh;
            int qg = q0 + r;
            if (qg < N_TOK) {
                float inv = __fdividef(1.f, s_l[r]);
                float2 val = make_float2(o[mi][2 * hh] * inv,
                                         o[mi][2 * hh + 1] * inv);
                *(float2*)(g_ctx + ((size_t)b * N_TOK + qg) * EMBED + h * HD + col) = val;
            }
        }
    }
}

/* ---------------- launch -------------------------------------------------- */
extern "C" void kernel_launch(void* const* d_in, const int* in_sizes, int n_in,
                              void* d_out, int out_size) {
    const float* x_in    = (const float*)d_in[0];
    const float* x_cross = (const float*)d_in[1];
    const float* mask    = (const float*)d_in[2];
    const float* q_w     = (const float*)d_in[3];
    const float* kv_w    = (const float*)d_in[4];
    const float* proj_w  = (const float*)d_in[5];
    const float* proj_b  = (const float*)d_in[6];
    const float* table   = (const float*)d_in[7];
    const int*   rel     = (const int*)d_in[8];
    float* out = (float*)d_out;

    bias_gather_kernel<<<(N_TOK * N_TOK + 255) / 256, 256>>>(table, rel);
    mask_T_kernel<<<(NWIN * N_TOK * N_TOK + 255) / 256, 256>>>(mask);
    gemm_qkv_kernel<<<dim3(M_ROWS / 64, 9), 256>>>(x_in, x_cross, q_w, kv_w);
    attn_mma_kernel<<<BATCH * HEADS * NQT, 256>>>();
    gemm_proj_kernel<<<dim3(M_ROWS / 64, 3), 256>>>(proj_w, proj_b, out);
}

// round 7
// speedup vs baseline: 2.0929x; 1.0167x over previous
#include <cuda_runtime.h>
#include <cstdint>

#define N_TOK 343
#define EMBED 192
#define HEADS 6
#define HD 32
#define BATCH 256
#define NWIN 64
#define QSCALE 0.17677669529663687f  /* 32^-0.5 */

#define M_ROWS (BATCH * N_TOK)        /* 87808 = 1372*64 */
#define NKT 6                          /* 384 = 6*64 k tiles */
#define NQT 6                          /* 6 q tiles */

/* attn dynamic smem layout (floats) */
#define OFF_QS    0                    /* 64*36 uint  */
#define OFF_KS    (OFF_QS + 64 * 36)   /* 64*36 uint  */
#define OFF_VS    (OFF_KS + 64 * 36)   /* 32*68 uint  */
#define OFF_STG   (OFF_VS + 32 * 68)   /* 64*68 float */
#define OFF_BM    (OFF_STG + 64 * 68)  /* 64*68 float */
#define OFF_SM    (OFF_BM + 64 * 68)   /* 64 */
#define OFF_SL    (OFF_SM + 64)        /* 64 */
#define OFF_SA    (OFF_SL + 64)        /* 64 */
#define SMEM_ATTN ((OFF_SA + 64) * 4)  /* 62720 B */

/* ---------------- scratch (device globals) ------------------------------- */
__device__ float g_q[BATCH * HEADS * N_TOK * HD];     // [b,h,n,d] (scaled)
__device__ float g_k[BATCH * HEADS * N_TOK * HD];
__device__ float g_v[BATCH * HEADS * N_TOK * HD];
__device__ float g_ctx[BATCH * N_TOK * EMBED];        // [b,n,c]
__device__ float g_bias_t[HEADS * N_TOK * N_TOK];     // [h,k,q]
__device__ float g_mask_t[NWIN * N_TOK * N_TOK];      // [w,k,q]

/* ---------------- helpers ------------------------------------------------- */
__device__ __forceinline__ uint32_t f2tf(float f) {
    uint32_t r;
    asm("cvt.rna.tf32.f32 %0, %1;" : "=r"(r) : "f"(f));
    return r;
}
__device__ __forceinline__ void mma_tf32(float c[4],
                                         uint32_t a0, uint32_t a1,
                                         uint32_t a2, uint32_t a3,
                                         uint32_t b0, uint32_t b1) {
    asm volatile(
        "mma.sync.aligned.m16n8k8.row.col.f32.tf32.tf32.f32 "
        "{%0,%1,%2,%3}, {%4,%5,%6,%7}, {%8,%9}, {%0,%1,%2,%3};"
        : "+f"(c[0]), "+f"(c[1]), "+f"(c[2]), "+f"(c[3])
        : "r"(a0), "r"(a1), "r"(a2), "r"(a3), "r"(b0), "r"(b1));
}

/* ---------------- bias gather / mask transpose --------------------------- */
__global__ void bias_gather_kernel(const float* __restrict__ table,
                                   const int* __restrict__ rel) {
    int i = blockIdx.x * blockDim.x + threadIdx.x;   // i = k*N + q
    if (i >= N_TOK * N_TOK) return;
    int q = i % N_TOK;
    int k = i / N_TOK;
    int r = rel[q * N_TOK + k];
#pragma unroll
    for (int h = 0; h < HEADS; ++h)
        g_bias_t[h * N_TOK * N_TOK + i] = table[r * HEADS + h];
}

__global__ void mask_T_kernel(const float* __restrict__ mask) {
    int idx = blockIdx.x * blockDim.x + threadIdx.x;
    if (idx >= NWIN * N_TOK * N_TOK) return;
    int q = idx % N_TOK;
    int t = idx / N_TOK;
    int k = t % N_TOK;
    int w = t / N_TOK;
    g_mask_t[idx] = mask[((size_t)w * N_TOK + q) * N_TOK + k];
}

/* ------- warp-MMA tf32 GEMM core (validated round 5) --------------------- */
__device__ __forceinline__ void mma_gemm_tile(const float* __restrict__ A,
                                              const float* __restrict__ W,
                                              int m0, int n0,
                                              float* As, float* Bs,
                                              float* Stage) {
    const int tid = threadIdx.x;
    const int lane = tid & 31, warp = tid >> 5;
    const int wm = warp & 1, wn = warp >> 1;
    const int g = lane >> 2, t = lane & 3;
    const uint32_t* Au = (const uint32_t*)As;
    const uint32_t* Bu = (const uint32_t*)Bs;

    float c[2][2][4];
#pragma unroll
    for (int mi = 0; mi < 2; ++mi)
#pragma unroll
        for (int ni = 0; ni < 2; ++ni)
#pragma unroll
            for (int e = 0; e < 4; ++e) c[mi][ni][e] = 0.f;

#pragma unroll 1
    for (int kt = 0; kt < 6; ++kt) {
        const int k0 = kt * 32;
#pragma unroll
        for (int r = 0; r < 2; ++r) {
            int idx = tid + 256 * r;
            int row = idx >> 3, kq = idx & 7;
            float4 av = *(const float4*)(A + (size_t)(m0 + row) * EMBED + k0 + kq * 4);
            float4 wv = *(const float4*)(W + (size_t)(n0 + row) * EMBED + k0 + kq * 4);
            uint4 ta, tb;
            ta.x = f2tf(av.x); ta.y = f2tf(av.y); ta.z = f2tf(av.z); ta.w = f2tf(av.w);
            tb.x = f2tf(wv.x); tb.y = f2tf(wv.y); tb.z = f2tf(wv.z); tb.w = f2tf(wv.w);
            *(uint4*)(As + row * 36 + kq * 4) = ta;
            *(uint4*)(Bs + row * 36 + kq * 4) = tb;
        }
        __syncthreads();
#pragma unroll
        for (int ks = 0; ks < 4; ++ks) {
            const int k = ks * 8;
            uint32_t a[2][4], b[2][2];
#pragma unroll
            for (int mi = 0; mi < 2; ++mi) {
                int mb = wm * 32 + mi * 16;
                a[mi][0] = Au[(mb + g) * 36 + k + t];
                a[mi][1] = Au[(mb + 8 + g) * 36 + k + t];
                a[mi][2] = Au[(mb + g) * 36 + k + 4 + t];
                a[mi][3] = Au[(mb + 8 + g) * 36 + k + 4 + t];
            }
#pragma unroll
            for (int ni = 0; ni < 2; ++ni) {
                int nb = wn * 16 + ni * 8;
                b[ni][0] = Bu[(nb + g) * 36 + k + t];
                b[ni][1] = Bu[(nb + g) * 36 + k + 4 + t];
            }
#pragma unroll
            for (int mi = 0; mi < 2; ++mi)
#pragma unroll
                for (int ni = 0; ni < 2; ++ni)
                    mma_tf32(c[mi][ni], a[mi][0], a[mi][1], a[mi][2], a[mi][3],
                             b[ni][0], b[ni][1]);
        }
        __syncthreads();
    }

#pragma unroll
    for (int mi = 0; mi < 2; ++mi)
#pragma unroll
        for (int ni = 0; ni < 2; ++ni) {
            int row = wm * 32 + mi * 16 + g;
            int col = wn * 16 + ni * 8 + 2 * t;
            Stage[row * 65 + col]       = c[mi][ni][0];
            Stage[row * 65 + col + 1]   = c[mi][ni][1];
            Stage[(row + 8) * 65 + col]     = c[mi][ni][2];
            Stage[(row + 8) * 65 + col + 1] = c[mi][ni][3];
        }
    __syncthreads();
}

/* ---------------- fused Q + KV projections (tensor-core) ----------------- */
__global__ __launch_bounds__(256) void gemm_qkv_kernel(
    const float* __restrict__ x_in, const float* __restrict__ x_cross,
    const float* __restrict__ q_w, const float* __restrict__ kv_w) {
    __shared__ float As[64 * 36];
    __shared__ float Bs[64 * 36];
    __shared__ float Stage[64 * 65];
    const int tid = threadIdx.x;
    const int m0 = blockIdx.x * 64;
    const int yt = blockIdx.y;
    const bool isq = (yt < 3);
    const float* A = isq ? x_in : x_cross;
    const float* W = isq ? q_w : kv_w;
    const int n0 = isq ? yt * 64 : (yt - 3) * 64;

    mma_gemm_tile(A, W, m0, n0, As, Bs, Stage);

#pragma unroll 4
    for (int j = 0; j < 16; ++j) {
        int i = tid + 256 * j;
        int ml = i >> 6, cc = i & 63;
        float v = Stage[ml * 65 + cc];
        int m = m0 + ml;
        int bb = m / N_TOK;
        int nn = m - bb * N_TOK;
        int n = n0 + cc;
        if (isq) {
            int h = n >> 5, d = n & 31;
            g_q[((size_t)(bb * HEADS + h) * N_TOK + nn) * HD + d] = v * QSCALE;
        } else {
            int nc = (n < EMBED) ? n : n - EMBED;
            float* dst = (n < EMBED) ? g_k : g_v;
            int h = nc >> 5, d = nc & 31;
            dst[((size_t)(bb * HEADS + h) * N_TOK + nn) * HD + d] = v;
        }
    }
}

/* ---------------- output projection (tensor-core) ------------------------ */
__global__ __launch_bounds__(256) void gemm_proj_kernel(
    const float* __restrict__ proj_w, const float* __restrict__ proj_b,
    float* __restrict__ out) {
    __shared__ float As[64 * 36];
    __shared__ float Bs[64 * 36];
    __shared__ float Stage[64 * 65];
    const int tid = threadIdx.x;
    const int m0 = blockIdx.x * 64;
    const int n0 = blockIdx.y * 64;

    mma_gemm_tile(g_ctx, proj_w, m0, n0, As, Bs, Stage);

#pragma unroll 4
    for (int j = 0; j < 16; ++j) {
        int i = tid + 256 * j;
        int ml = i >> 6, cc = i & 63;
        int m = m0 + ml;
        int n = n0 + cc;
        out[(size_t)m * EMBED + n] = Stage[ml * 65 + cc] + proj_b[n];
    }
}

/* ---------------- tensor-core flash attention -----------------------------
   One CTA per (b, h, q-tile of 64). 256 threads = 8 warps.
   S tile 64x64 via mma tf32, Stage[k][q] stride 68.
   BM[k][q] = bias+mask preloaded into smem (coalesced) alongside K/V.
   Softmax writes P as tf32 BITS; PV A-fragments are raw LDS (no cvt).     */
__global__ __launch_bounds__(256, 2) void attn_mma_kernel() {
    extern __shared__ float smf[];
    uint32_t* Qs = (uint32_t*)(smf + OFF_QS);
    uint32_t* Ks = (uint32_t*)(smf + OFF_KS);
    uint32_t* Vs = (uint32_t*)(smf + OFF_VS);
    float* Stage = smf + OFF_STG;
    float* BM    = smf + OFF_BM;
    float* s_m   = smf + OFF_SM;
    float* s_l   = smf + OFF_SL;
    float* s_al  = smf + OFF_SA;

    const int bid = blockIdx.x;
    const int qt = bid % NQT;
    const int bh = bid / NQT;
    const int b  = bh / HEADS;
    const int h  = bh - b * HEADS;
    const int w  = b & (NWIN - 1);
    const int q0 = qt * 64;

    const int tid = threadIdx.x;
    const int lane = tid & 31, warp = tid >> 5;
    const int g = lane >> 2, t = lane & 3;
    const int wm = warp & 1, wn = warp >> 1;

    const float* Qg = g_q + (size_t)bh * N_TOK * HD;
    const float* Kg = g_k + (size_t)bh * N_TOK * HD;
    const float* Vg = g_v + (size_t)bh * N_TOK * HD;
    const float* biasp = g_bias_t + (size_t)h * N_TOK * N_TOK;
    const float* maskp = g_mask_t + (size_t)w * N_TOK * N_TOK;

    /* Q tile -> Qs[row][36] tf32 (rows >= N_TOK zeroed) */
#pragma unroll
    for (int r = 0; r < 2; ++r) {
        int idx = tid + 256 * r;
        int row = idx >> 3, c4 = idx & 7;
        int qg = q0 + row;
        float4 v = (qg < N_TOK) ? *(const float4*)(Qg + (size_t)qg * HD + c4 * 4)
                                : make_float4(0.f, 0.f, 0.f, 0.f);
        uint4 tv;
        tv.x = f2tf(v.x); tv.y = f2tf(v.y); tv.z = f2tf(v.z); tv.w = f2tf(v.w);
        *(uint4*)(Qs + row * 36 + c4 * 4) = tv;
    }
    if (tid < 64) { s_m[tid] = -1e30f; s_l[tid] = 0.f; }

    float o[2][4];
#pragma unroll
    for (int mi = 0; mi < 2; ++mi)
#pragma unroll
        for (int e = 0; e < 4; ++e) o[mi][e] = 0.f;

    /* loop-invariant softmax addressing: q = tid>>2, col base tq */
    const int sq = tid >> 2, stq = tid & 3;
    float* StgB = Stage + stq * 68 + sq;
    float* BMB  = BM + stq * 68 + sq;

#pragma unroll 1
    for (int kt = 0; kt < NKT; ++kt) {
        const int k0 = kt * 64;
        __syncthreads();                  /* prev PV done; smem free */

        /* K tile -> Ks[token][36] tf32 ; V tile -> Vs[d][token] tf32 */
#pragma unroll
        for (int r = 0; r < 2; ++r) {
            int idx = tid + 256 * r;
            int row = idx >> 3, c4 = idx & 7;
            int kg = k0 + row;
            float4 kv = (kg < N_TOK) ? *(const float4*)(Kg + (size_t)kg * HD + c4 * 4)
                                     : make_float4(0.f, 0.f, 0.f, 0.f);
            uint4 tk;
            tk.x = f2tf(kv.x); tk.y = f2tf(kv.y); tk.z = f2tf(kv.z); tk.w = f2tf(kv.w);
            *(uint4*)(Ks + row * 36 + c4 * 4) = tk;

            float4 vv = (kg < N_TOK) ? *(const float4*)(Vg + (size_t)kg * HD + c4 * 4)
                                     : make_float4(0.f, 0.f, 0.f, 0.f);
            int d = c4 * 4;
            Vs[(d + 0) * 68 + row] = f2tf(vv.x);
            Vs[(d + 1) * 68 + row] = f2tf(vv.y);
            Vs[(d + 2) * 68 + row] = f2tf(vv.z);
            Vs[(d + 3) * 68 + row] = f2tf(vv.w);
        }

        /* BM[k][q] = bias + mask (coalesced in q; -1e30 pads) */
#pragma unroll
        for (int j = 0; j < 16; ++j) {
            int i = tid + 256 * j;
            int kk = i >> 6, qq = i & 63;
            int kg = k0 + kk, qg = q0 + qq;
            float v = -1e30f;
            if (kg < N_TOK && qg < N_TOK) {
                size_t a = (size_t)kg * N_TOK + qg;
                v = biasp[a] + maskp[a];
            }
            BM[kk * 68 + qq] = v;
        }
        __syncthreads();

        /* S = Q K^T : warps 2m x 4n, warp tile 32x16, K=32 (4 ksteps) */
        {
            float c[2][2][4];
#pragma unroll
            for (int mi = 0; mi < 2; ++mi)
#pragma unroll
                for (int ni = 0; ni < 2; ++ni)
#pragma unroll
                    for (int e = 0; e < 4; ++e) c[mi][ni][e] = 0.f;
#pragma unroll
            for (int ks = 0; ks < 4; ++ks) {
                const int k = ks * 8;
                uint32_t a[2][4], bf[2][2];
#pragma unroll
                for (int mi = 0; mi < 2; ++mi) {
                    int mb = wm * 32 + mi * 16;
                    a[mi][0] = Qs[(mb + g) * 36 + k + t];
                    a[mi][1] = Qs[(mb + 8 + g) * 36 + k + t];
                    a[mi][2] = Qs[(mb + g) * 36 + k + 4 + t];
                    a[mi][3] = Qs[(mb + 8 + g) * 36 + k + 4 + t];
                }
#pragma unroll
                for (int ni = 0; ni < 2; ++ni) {
                    int nb = wn * 16 + ni * 8;
                    bf[ni][0] = Ks[(nb + g) * 36 + k + t];
                    bf[ni][1] = Ks[(nb + g) * 36 + k + 4 + t];
                }
#pragma unroll
                for (int mi = 0; mi < 2; ++mi)
#pragma unroll
                    for (int ni = 0; ni < 2; ++ni)
                        mma_tf32(c[mi][ni], a[mi][0], a[mi][1], a[mi][2], a[mi][3],
                                 bf[ni][0], bf[ni][1]);
            }
#pragma unroll
            for (int mi = 0; mi < 2; ++mi)
#pragma unroll
                for (int ni = 0; ni < 2; ++ni) {
                    int row = wm * 32 + mi * 16 + g;
                    int col = wn * 16 + ni * 8 + 2 * t;
                    Stage[col * 68 + row]           = c[mi][ni][0];
                    Stage[(col + 1) * 68 + row]     = c[mi][ni][1];
                    Stage[col * 68 + row + 8]       = c[mi][ni][2];
                    Stage[(col + 1) * 68 + row + 8] = c[mi][ni][3];
                }
        }
        __syncthreads();

        /* softmax: q = tid>>2, k = tq+4j; S+BM, online m/l; store P as tf32 bits */
        {
            float sv[16];
            float mx = -1e30f;
#pragma unroll
            for (int j = 0; j < 16; ++j) {
                sv[j] = StgB[272 * j] + BMB[272 * j];
                mx = fmaxf(mx, sv[j]);
            }
            mx = fmaxf(mx, __shfl_xor_sync(0xFFFFFFFFu, mx, 1));
            mx = fmaxf(mx, __shfl_xor_sync(0xFFFFFFFFu, mx, 2));
            float mold = s_m[sq];
            float newm = fmaxf(mold, mx);
            float sum = 0.f;
#pragma unroll
            for (int j = 0; j < 16; ++j) {
                float p = __expf(sv[j] - newm);
                sum += p;
                StgB[272 * j] = __uint_as_float(f2tf(p));
            }
            sum += __shfl_xor_sync(0xFFFFFFFFu, sum, 1);
            sum += __shfl_xor_sync(0xFFFFFFFFu, sum, 2);
            if (stq == 0) {
                float alpha = __expf(mold - newm);
                s_al[sq] = alpha;
                s_l[sq] = s_l[sq] * alpha + sum;
                s_m[sq] = newm;
            }
        }
        __syncthreads();

        /* PV: O = alpha*O + P @ V ; P bits read directly (no cvt) */
        {
            const uint32_t* StgU = (const uint32_t*)Stage;
#pragma unroll
            for (int mi = 0; mi < 2; ++mi) {
                int r0 = wm * 32 + mi * 16 + g;
                float a0 = s_al[r0], a1 = s_al[r0 + 8];
                o[mi][0] *= a0; o[mi][1] *= a0;
                o[mi][2] *= a1; o[mi][3] *= a1;
            }
            const int nb = wn * 8;
#pragma unroll
            for (int ks = 0; ks < 8; ++ks) {
                const int k = ks * 8;
                uint32_t b0 = Vs[(nb + g) * 68 + k + t];
                uint32_t b1 = Vs[(nb + g) * 68 + k + 4 + t];
#pragma unroll
                for (int mi = 0; mi < 2; ++mi) {
                    int mb = wm * 32 + mi * 16;
                    uint32_t a0 = StgU[(k + t) * 68 + mb + g];
                    uint32_t a1 = StgU[(k + t) * 68 + mb + 8 + g];
                    uint32_t a2 = StgU[(k + 4 + t) * 68 + mb + g];
                    uint32_t a3 = StgU[(k + 4 + t) * 68 + mb + 8 + g];
                    mma_tf32(o[mi], a0, a1, a2, a3, b0, b1);
                }
            }
        }
    }
    __syncthreads();

    /* normalize + write O fragments to g_ctx */
#pragma unroll
    for (int mi = 0; mi < 2; ++mi) {
        int r0 = wm * 32 + mi * 16 + g;
        int col = wn * 8 + 2 * t;
#pragma unroll
        for (int hh = 0; hh < 2; ++hh) {
            int r = r0 + 8 * hh;
            int qg = q0 + r;
            if (qg < N_TOK) {
                float inv = __fdividef(1.f, s_l[r]);
                float2 val = make_float2(o[mi][2 * hh] * inv,
                                         o[mi][2 * hh + 1] * inv);
                *(float2*)(g_ctx + ((size_t)b * N_TOK + qg) * EMBED + h * HD + col) = val;
            }
        }
    }
}

/* ---------------- launch -------------------------------------------------- */
extern "C" void kernel_launch(void* const* d_in, const int* in_sizes, int n_in,
                              void* d_out, int out_size) {
    const float* x_in    = (const float*)d_in[0];
    const float* x_cross = (const float*)d_in[1];
    const float* mask    = (const float*)d_in[2];
    const float* q_w     = (const float*)d_in[3];
    const float* kv_w    = (const float*)d_in[4];
    const float* proj_w  = (const float*)d_in[5];
    const float* proj_b  = (const float*)d_in[6];
    const float* table   = (const float*)d_in[7];
    const int*   rel     = (const int*)d_in[8];
    float* out = (float*)d_out;

    cudaFuncSetAttribute(attn_mma_kernel,
                         cudaFuncAttributeMaxDynamicSharedMemorySize, SMEM_ATTN);

    bias_gather_kernel<<<(N_TOK * N_TOK + 255) / 256, 256>>>(table, rel);
    mask_T_kernel<<<(NWIN * N_TOK * N_TOK + 255) / 256, 256>>>(mask);
    gemm_qkv_kernel<<<dim3(M_ROWS / 64, 9), 256>>>(x_in, x_cross, q_w, kv_w);
    attn_mma_kernel<<<BATCH * HEADS * NQT, 256, SMEM_ATTN>>>();
    gemm_proj_kernel<<<dim3(M_ROWS / 64, 3), 256>>>(proj_w, proj_b, out);
}

// round 8
// speedup vs baseline: 3.4858x; 1.6656x over previous
#include <cuda_runtime.h>
#include <cstdint>

#define N_TOK 343
#define EMBED 192
#define HEADS 6
#define HD 32
#define BATCH 256
#define NWIN 64
#define QSCALE 0.17677669529663687f  /* 32^-0.5 */

#define M_ROWS (BATCH * N_TOK)        /* 87808 = 1372*64 */
#define NKT 6                          /* 384 = 6*64 k tiles */
#define QT_ROWS 128
#define NQT3 3                         /* ceil(343/128) */
#define PADK 344                       /* padded k stride (even -> float2 ok) */
#define PADQ 384                       /* padded q rows */

/* ---------------- scratch (device globals) ------------------------------- */
__device__ float g_q[BATCH * HEADS * N_TOK * HD];     // [b,h,n,d] (scaled)
__device__ float g_k[BATCH * HEADS * N_TOK * HD];
__device__ float g_v[BATCH * HEADS * N_TOK * HD];
__device__ float g_ctx[BATCH * N_TOK * EMBED];        // [b,n,c]
__device__ float g_biasp[HEADS * PADQ * PADK];        // [h,q,k] padded
__device__ float g_maskp[NWIN * PADQ * PADK];         // [w,q,k] padded

/* ---------------- helpers ------------------------------------------------- */
__device__ __forceinline__ uint32_t f2tf(float f) {
    uint32_t r;
    asm("cvt.rna.tf32.f32 %0, %1;" : "=r"(r) : "f"(f));
    return r;
}
/* pack two floats -> f16x2; 'lo' in lower half (order consistent everywhere) */
__device__ __forceinline__ uint32_t packh2(float lo, float hi) {
    uint32_t r;
    asm("cvt.rn.f16x2.f32 %0, %2, %1;" : "=r"(r) : "f"(lo), "f"(hi));
    return r;
}
__device__ __forceinline__ void mma_tf32(float c[4],
                                         uint32_t a0, uint32_t a1,
                                         uint32_t a2, uint32_t a3,
                                         uint32_t b0, uint32_t b1) {
    asm volatile(
        "mma.sync.aligned.m16n8k8.row.col.f32.tf32.tf32.f32 "
        "{%0,%1,%2,%3}, {%4,%5,%6,%7}, {%8,%9}, {%0,%1,%2,%3};"
        : "+f"(c[0]), "+f"(c[1]), "+f"(c[2]), "+f"(c[3])
        : "r"(a0), "r"(a1), "r"(a2), "r"(a3), "r"(b0), "r"(b1));
}
__device__ __forceinline__ void mma_f16(float c[4],
                                        uint32_t a0, uint32_t a1,
                                        uint32_t a2, uint32_t a3,
                                        uint32_t b0, uint32_t b1) {
    asm volatile(
        "mma.sync.aligned.m16n8k16.row.col.f32.f16.f16.f32 "
        "{%0,%1,%2,%3}, {%4,%5,%6,%7}, {%8,%9}, {%0,%1,%2,%3};"
        : "+f"(c[0]), "+f"(c[1]), "+f"(c[2]), "+f"(c[3])
        : "r"(a0), "r"(a1), "r"(a2), "r"(a3), "r"(b0), "r"(b1));
}

/* ---------------- bias gather / mask pad (k-stride 344) ------------------ */
__global__ void bias_gather_kernel(const float* __restrict__ table,
                                   const int* __restrict__ rel) {
    int i = blockIdx.x * blockDim.x + threadIdx.x;   // i = q*343 + k
    if (i >= N_TOK * N_TOK) return;
    int k = i % N_TOK;
    int q = i / N_TOK;
    int r = rel[i];
#pragma unroll
    for (int h = 0; h < HEADS; ++h)
        g_biasp[((size_t)h * PADQ + q) * PADK + k] = table[r * HEADS + h];
}

__global__ void mask_pad_kernel(const float* __restrict__ mask) {
    int idx = blockIdx.x * blockDim.x + threadIdx.x;  // (w*343 + q)*343 + k
    if (idx >= NWIN * N_TOK * N_TOK) return;
    int k = idx % N_TOK;
    int t = idx / N_TOK;
    int q = t % N_TOK;
    int w = t / N_TOK;
    g_maskp[((size_t)w * PADQ + q) * PADK + k] = mask[idx];
}

/* ------- warp-MMA tf32 GEMM core (validated round 5) --------------------- */
__device__ __forceinline__ void mma_gemm_tile(const float* __restrict__ A,
                                              const float* __restrict__ W,
                                              int m0, int n0, int tid,
                                              float* As, float* Bs,
                                              float* Stage) {
    const int lane = tid & 31, warp = tid >> 5;
    const int wm = warp & 1, wn = warp >> 1;
    const int g = lane >> 2, t = lane & 3;
    const uint32_t* Au = (const uint32_t*)As;
    const uint32_t* Bu = (const uint32_t*)Bs;

    float c[2][2][4];
#pragma unroll
    for (int mi = 0; mi < 2; ++mi)
#pragma unroll
        for (int ni = 0; ni < 2; ++ni)
#pragma unroll
            for (int e = 0; e < 4; ++e) c[mi][ni][e] = 0.f;

#pragma unroll 1
    for (int kt = 0; kt < 6; ++kt) {
        const int k0 = kt * 32;
#pragma unroll
        for (int r = 0; r < 2; ++r) {
            int idx = tid + 256 * r;
            int row = idx >> 3, kq = idx & 7;
            float4 av = *(const float4*)(A + (size_t)(m0 + row) * EMBED + k0 + kq * 4);
            float4 wv = *(const float4*)(W + (size_t)(n0 + row) * EMBED + k0 + kq * 4);
            uint4 ta, tb;
            ta.x = f2tf(av.x); ta.y = f2tf(av.y); ta.z = f2tf(av.z); ta.w = f2tf(av.w);
            tb.x = f2tf(wv.x); tb.y = f2tf(wv.y); tb.z = f2tf(wv.z); tb.w = f2tf(wv.w);
            *(uint4*)(As + row * 36 + kq * 4) = ta;
            *(uint4*)(Bs + row * 36 + kq * 4) = tb;
        }
        __syncthreads();
#pragma unroll
        for (int ks = 0; ks < 4; ++ks) {
            const int k = ks * 8;
            uint32_t a[2][4], b[2][2];
#pragma unroll
            for (int mi = 0; mi < 2; ++mi) {
                int mb = wm * 32 + mi * 16;
                a[mi][0] = Au[(mb + g) * 36 + k + t];
                a[mi][1] = Au[(mb + 8 + g) * 36 + k + t];
                a[mi][2] = Au[(mb + g) * 36 + k + 4 + t];
                a[mi][3] = Au[(mb + 8 + g) * 36 + k + 4 + t];
            }
#pragma unroll
            for (int ni = 0; ni < 2; ++ni) {
                int nb = wn * 16 + ni * 8;
                b[ni][0] = Bu[(nb + g) * 36 + k + t];
                b[ni][1] = Bu[(nb + g) * 36 + k + 4 + t];
            }
#pragma unroll
            for (int mi = 0; mi < 2; ++mi)
#pragma unroll
                for (int ni = 0; ni < 2; ++ni)
                    mma_tf32(c[mi][ni], a[mi][0], a[mi][1], a[mi][2], a[mi][3],
                             b[ni][0], b[ni][1]);
        }
        __syncthreads();
    }

#pragma unroll
    for (int mi = 0; mi < 2; ++mi)
#pragma unroll
        for (int ni = 0; ni < 2; ++ni) {
            int row = wm * 32 + mi * 16 + g;
            int col = wn * 16 + ni * 8 + 2 * t;
            Stage[row * 65 + col]       = c[mi][ni][0];
            Stage[row * 65 + col + 1]   = c[mi][ni][1];
            Stage[(row + 8) * 65 + col]     = c[mi][ni][2];
            Stage[(row + 8) * 65 + col + 1] = c[mi][ni][3];
        }
    __syncthreads();
}

/* ---------------- fused Q + KV projections (tensor-core) ----------------- */
__global__ __launch_bounds__(256) void gemm_qkv_kernel(
    const float* __restrict__ x_in, const float* __restrict__ x_cross,
    const float* __restrict__ q_w, const float* __restrict__ kv_w) {
    __shared__ float As[64 * 36];
    __shared__ float Bs[64 * 36];
    __shared__ float Stage[64 * 65];
    const int tid = threadIdx.x;
    const int m0 = blockIdx.x * 64;
    const int yt = blockIdx.y;
    const bool isq = (yt < 3);
    const float* A = isq ? x_in : x_cross;
    const float* W = isq ? q_w : kv_w;
    const int n0 = isq ? yt * 64 : (yt - 3) * 64;

    mma_gemm_tile(A, W, m0, n0, tid, As, Bs, Stage);

#pragma unroll 4
    for (int j = 0; j < 16; ++j) {
        int i = tid + 256 * j;
        int ml = i >> 6, cc = i & 63;
        float v = Stage[ml * 65 + cc];
        int m = m0 + ml;
        int bb = m / N_TOK;
        int nn = m - bb * N_TOK;
        int n = n0 + cc;
        if (isq) {
            int h = n >> 5, d = n & 31;
            g_q[((size_t)(bb * HEADS + h) * N_TOK + nn) * HD + d] = v * QSCALE;
        } else {
            int nc = (n < EMBED) ? n : n - EMBED;
            float* dst = (n < EMBED) ? g_k : g_v;
            int h = nc >> 5, d = nc & 31;
            dst[((size_t)(bb * HEADS + h) * N_TOK + nn) * HD + d] = v;
        }
    }
}

/* ---------------- output projection (tensor-core) ------------------------ */
__global__ __launch_bounds__(256) void gemm_proj_kernel(
    const float* __restrict__ proj_w, const float* __restrict__ proj_b,
    float* __restrict__ out) {
    __shared__ float As[64 * 36];
    __shared__ float Bs[64 * 36];
    __shared__ float Stage[64 * 65];
    const int tid = threadIdx.x;
    const int m0 = blockIdx.x * 64;
    const int n0 = blockIdx.y * 64;

    mma_gemm_tile(g_ctx, proj_w, m0, n0, tid, As, Bs, Stage);

#pragma unroll 4
    for (int j = 0; j < 16; ++j) {
        int i = tid + 256 * j;
        int ml = i >> 6, cc = i & 63;
        int m = m0 + ml;
        int n = n0 + cc;
        out[(size_t)m * EMBED + n] = Stage[ml * 65 + cc] + proj_b[n];
    }
}

/* ---------------- fp16 register-resident flash attention ------------------
   One CTA per (b, h, q-tile of 128). 8 warps x 16 rows each (rows-only split:
   every warp owns its rows' FULL k-width). S lives in C-fragments; softmax in
   registers (quad shuffles); P packs directly into fp16 A-fragments (layout
   identity); bias+mask loaded as float2 from padded gmem into fragments.    */
__global__ __launch_bounds__(256, 2) void attn_fp16_kernel() {
    __shared__ uint32_t Qs[128 * 20];   /* [row][d-pair], stride 20 h2-words */
    __shared__ uint32_t Ks[64 * 20];    /* [tok][d-pair] */
    __shared__ uint32_t Vs[32 * 36];    /* [d][tok-pair], stride 36 */

    const int bid = blockIdx.x;
    const int qt = bid % NQT3;
    const int bh = bid / NQT3;
    const int b  = bh / HEADS;
    const int h  = bh - b * HEADS;
    const int w  = b & (NWIN - 1);
    const int q0 = qt * QT_ROWS;

    const int tid = threadIdx.x;
    const int lane = tid & 31, warp = tid >> 5;
    const int g = lane >> 2, t = lane & 3;
    const int mrow = warp * 16;          /* warp's first row in tile */

    const float* Qg = g_q + (size_t)bh * N_TOK * HD;
    const float* Kg = g_k + (size_t)bh * N_TOK * HD;
    const float* Vg = g_v + (size_t)bh * N_TOK * HD;

    const int qrow0 = q0 + mrow + g;     /* global q row of frag row g   */
    const float* br0 = g_biasp + ((size_t)h * PADQ + qrow0) * PADK;
    const float* br1 = br0 + 8 * PADK;
    const float* mr0 = g_maskp + ((size_t)w * PADQ + qrow0) * PADK;
    const float* mr1 = mr0 + 8 * PADK;

    /* ---- Q tile [128x32] -> Qs fp16 (zero-pad rows >= N_TOK) ---- */
#pragma unroll
    for (int r = 0; r < 4; ++r) {
        int idx = tid + 256 * r;
        int row = idx >> 3, c4 = idx & 7;
        int qg = q0 + row;
        float4 v = (qg < N_TOK) ? *(const float4*)(Qg + (size_t)qg * HD + c4 * 4)
                                : make_float4(0.f, 0.f, 0.f, 0.f);
        uint2 p;
        p.x = packh2(v.x, v.y);
        p.y = packh2(v.z, v.w);
        *(uint2*)(Qs + row * 20 + c4 * 2) = p;
    }
    __syncthreads();

    /* ---- Q A-fragments (held in regs across all k-tiles) ---- */
    uint32_t qa[2][4];
#pragma unroll
    for (int ks = 0; ks < 2; ++ks) {
        qa[ks][0] = Qs[(mrow + g) * 20 + 8 * ks + t];
        qa[ks][1] = Qs[(mrow + 8 + g) * 20 + 8 * ks + t];
        qa[ks][2] = Qs[(mrow + g) * 20 + 8 * ks + t + 4];
        qa[ks][3] = Qs[(mrow + 8 + g) * 20 + 8 * ks + t + 4];
    }

    float m0r = -1e30f, m1r = -1e30f, l0 = 0.f, l1 = 0.f;
    float o[4][4];
#pragma unroll
    for (int nd = 0; nd < 4; ++nd)
#pragma unroll
        for (int e = 0; e < 4; ++e) o[nd][e] = 0.f;

#pragma unroll 1
    for (int kt = 0; kt < NKT; ++kt) {
        const int k0 = kt * 64;
        __syncthreads();                 /* prev PV done: Ks/Vs reusable */

        /* K fill [64x32] fp16 */
#pragma unroll
        for (int r = 0; r < 2; ++r) {
            int idx = tid + 256 * r;
            int row = idx >> 3, c4 = idx & 7;
            int kg = k0 + row;
            float4 v = (kg < N_TOK) ? *(const float4*)(Kg + (size_t)kg * HD + c4 * 4)
                                    : make_float4(0.f, 0.f, 0.f, 0.f);
            uint2 p;
            p.x = packh2(v.x, v.y);
            p.y = packh2(v.z, v.w);
            *(uint2*)(Ks + row * 20 + c4 * 2) = p;
        }
        /* V fill, transposed [d][tok-pairs]: thread d=tid&31, token-seg tid>>5 */
        {
            int d = tid & 31;
            int seg = tid >> 5;
            float vv[8];
#pragma unroll
            for (int s = 0; s < 8; ++s) {
                int kg = k0 + seg * 8 + s;
                vv[s] = (kg < N_TOK) ? Vg[(size_t)kg * HD + d] : 0.f;
            }
#pragma unroll
            for (int p = 0; p < 4; ++p)
                Vs[d * 36 + seg * 4 + p] = packh2(vv[2 * p], vv[2 * p + 1]);
        }
        __syncthreads();

        /* S = Q K^T: 16 rows x 64 tokens per warp; c[ni][.] C-fragments */
        float c[8][4];
#pragma unroll
        for (int ni = 0; ni < 8; ++ni)
#pragma unroll
            for (int e = 0; e < 4; ++e) c[ni][e] = 0.f;
#pragma unroll
        for (int ks = 0; ks < 2; ++ks)
#pragma unroll
            for (int ni = 0; ni < 8; ++ni) {
                uint32_t b0 = Ks[(8 * ni + g) * 20 + 8 * ks + t];
                uint32_t b1 = Ks[(8 * ni + g) * 20 + 8 * ks + t + 4];
                mma_f16(c[ni], qa[ks][0], qa[ks][1], qa[ks][2], qa[ks][3], b0, b1);
            }

        /* bias + mask into fragments (padded arrays: rows always safe) */
        if (kt < NKT - 1) {
#pragma unroll
            for (int ni = 0; ni < 8; ++ni) {
                int off = k0 + 8 * ni + 2 * t;
                float2 b0v = *(const float2*)(br0 + off);
                float2 m0v = *(const float2*)(mr0 + off);
                float2 b1v = *(const float2*)(br1 + off);
                float2 m1v = *(const float2*)(mr1 + off);
                c[ni][0] += b0v.x + m0v.x;
                c[ni][1] += b0v.y + m0v.y;
                c[ni][2] += b1v.x + m1v.x;
                c[ni][3] += b1v.y + m1v.y;
            }
        } else {
#pragma unroll
            for (int ni = 0; ni < 8; ++ni) {
                int col = k0 + 8 * ni + 2 * t;
                if (col < N_TOK) {
                    c[ni][0] += br0[col] + mr0[col];
                    c[ni][2] += br1[col] + mr1[col];
                } else { c[ni][0] = -1e30f; c[ni][2] = -1e30f; }
                if (col + 1 < N_TOK) {
                    c[ni][1] += br0[col + 1] + mr0[col + 1];
                    c[ni][3] += br1[col + 1] + mr1[col + 1];
                } else { c[ni][1] = -1e30f; c[ni][3] = -1e30f; }
            }
        }

        /* register softmax: rows g (c0,c1) and g+8 (c2,c3) */
        float mx0 = -1e30f, mx1 = -1e30f;
#pragma unroll
        for (int ni = 0; ni < 8; ++ni) {
            mx0 = fmaxf(mx0, fmaxf(c[ni][0], c[ni][1]));
            mx1 = fmaxf(mx1, fmaxf(c[ni][2], c[ni][3]));
        }
        mx0 = fmaxf(mx0, __shfl_xor_sync(0xFFFFFFFFu, mx0, 1));
        mx0 = fmaxf(mx0, __shfl_xor_sync(0xFFFFFFFFu, mx0, 2));
        mx1 = fmaxf(mx1, __shfl_xor_sync(0xFFFFFFFFu, mx1, 1));
        mx1 = fmaxf(mx1, __shfl_xor_sync(0xFFFFFFFFu, mx1, 2));
        float newm0 = fmaxf(m0r, mx0), newm1 = fmaxf(m1r, mx1);
        float alpha0 = __expf(m0r - newm0), alpha1 = __expf(m1r - newm1);
        m0r = newm0; m1r = newm1;

        uint32_t paL[8], paH[8];
        float sum0 = 0.f, sum1 = 0.f;
#pragma unroll
        for (int ni = 0; ni < 8; ++ni) {
            float p0 = __expf(c[ni][0] - newm0);
            float p1 = __expf(c[ni][1] - newm0);
            float p2 = __expf(c[ni][2] - newm1);
            float p3 = __expf(c[ni][3] - newm1);
            sum0 += p0 + p1;
            sum1 += p2 + p3;
            paL[ni] = packh2(p0, p1);    /* A-frag rows g   */
            paH[ni] = packh2(p2, p3);    /* A-frag rows g+8 */
        }
        sum0 += __shfl_xor_sync(0xFFFFFFFFu, sum0, 1);
        sum0 += __shfl_xor_sync(0xFFFFFFFFu, sum0, 2);
        sum1 += __shfl_xor_sync(0xFFFFFFFFu, sum1, 1);
        sum1 += __shfl_xor_sync(0xFFFFFFFFu, sum1, 2);
        l0 = l0 * alpha0 + sum0;
        l1 = l1 * alpha1 + sum1;

        /* O = alpha*O + P @ V (P A-frags from regs; V B-frags from smem) */
#pragma unroll
        for (int nd = 0; nd < 4; ++nd) {
            o[nd][0] *= alpha0; o[nd][1] *= alpha0;
            o[nd][2] *= alpha1; o[nd][3] *= alpha1;
        }
#pragma unroll
        for (int kk = 0; kk < 4; ++kk)
#pragma unroll
            for (int nd = 0; nd < 4; ++nd) {
                uint32_t b0 = Vs[(8 * nd + g) * 36 + 8 * kk + t];
                uint32_t b1 = Vs[(8 * nd + g) * 36 + 8 * kk + t + 4];
                mma_f16(o[nd], paL[2 * kk], paH[2 * kk],
                        paL[2 * kk + 1], paH[2 * kk + 1], b0, b1);
            }
    }

    /* epilogue: normalize + write */
    float inv0 = __fdividef(1.f, l0);
    float inv1 = __fdividef(1.f, l1);
    int r0g = qrow0, r1g = qrow0 + 8;
#pragma unroll
    for (int nd = 0; nd < 4; ++nd) {
        int col = h * HD + 8 * nd + 2 * t;
        if (r0g < N_TOK) {
            float2 v = make_float2(o[nd][0] * inv0, o[nd][1] * inv0);
            *(float2*)(g_ctx + ((size_t)b * N_TOK + r0g) * EMBED + col) = v;
        }
        if (r1g < N_TOK) {
            float2 v = make_float2(o[nd][2] * inv1, o[nd][3] * inv1);
            *(float2*)(g_ctx + ((size_t)b * N_TOK + r1g) * EMBED + col) = v;
        }
    }
}

/* ---------------- launch -------------------------------------------------- */
extern "C" void kernel_launch(void* const* d_in, const int* in_sizes, int n_in,
                              void* d_out, int out_size) {
    const float* x_in    = (const float*)d_in[0];
    const float* x_cross = (const float*)d_in[1];
    const float* mask    = (const float*)d_in[2];
    const float* q_w     = (const float*)d_in[3];
    const float* kv_w    = (const float*)d_in[4];
    const float* proj_w  = (const float*)d_in[5];
    const float* proj_b  = (const float*)d_in[6];
    const float* table   = (const float*)d_in[7];
    const int*   rel     = (const int*)d_in[8];
    float* out = (float*)d_out;

    bias_gather_kernel<<<(N_TOK * N_TOK + 255) / 256, 256>>>(table, rel);
    mask_pad_kernel<<<(NWIN * N_TOK * N_TOK + 255) / 256, 256>>>(mask);
    gemm_qkv_kernel<<<dim3(M_ROWS / 64, 9), 256>>>(x_in, x_cross, q_w, kv_w);
    attn_fp16_kernel<<<BATCH * HEADS * NQT3, 256>>>();
    gemm_proj_kernel<<<dim3(M_ROWS / 64, 3), 256>>>(proj_w, proj_b, out);
}

// round 9
// speedup vs baseline: 4.6024x; 1.3203x over previous
#include <cuda_runtime.h>
#include <cuda_fp16.h>
#include <cstdint>

#define N_TOK 343
#define EMBED 192
#define HEADS 6
#define HD 32
#define BATCH 256
#define NWIN 64
#define QSCALE 0.17677669529663687f  /* 32^-0.5 */

#define M_ROWS (BATCH * N_TOK)        /* 87808 = 686*128 */
#define NKT 6                          /* 384 = 6*64 k tiles */
#define QT_ROWS 128
#define NQT3 3                         /* ceil(343/128) */
#define PADK 344                       /* padded k stride (even) */
#define PADQ 384                       /* padded q rows */

/* ---------------- scratch (device globals; zero-initialized) ------------- */
__device__ __half g_q[BATCH * HEADS * N_TOK * HD];    // [b,h,n,d] (scaled)
__device__ __half g_k[BATCH * HEADS * N_TOK * HD];
__device__ __half g_v[BATCH * HEADS * N_TOK * HD];
__device__ __half g_ctx[BATCH * N_TOK * EMBED];       // [b,n,c]
__device__ __half g_biasp[HEADS * PADQ * PADK];       // [h,q,k] padded
__device__ __half g_maskp[NWIN * PADQ * PADK];        // [w,q,k] padded

/* ---------------- helpers ------------------------------------------------- */
__device__ __forceinline__ uint32_t packh2(float lo, float hi) {
    uint32_t r;
    asm("cvt.rn.f16x2.f32 %0, %2, %1;" : "=r"(r) : "f"(lo), "f"(hi));
    return r;
}
__device__ __forceinline__ uint32_t h2pack(__half lo, __half hi) {
    return (uint32_t)__half_as_ushort(lo) | ((uint32_t)__half_as_ushort(hi) << 16);
}
__device__ __forceinline__ void mma_f16(float c[4],
                                        uint32_t a0, uint32_t a1,
                                        uint32_t a2, uint32_t a3,
                                        uint32_t b0, uint32_t b1) {
    asm volatile(
        "mma.sync.aligned.m16n8k16.row.col.f32.f16.f16.f32 "
        "{%0,%1,%2,%3}, {%4,%5,%6,%7}, {%8,%9}, {%0,%1,%2,%3};"
        : "+f"(c[0]), "+f"(c[1]), "+f"(c[2]), "+f"(c[3])
        : "r"(a0), "r"(a1), "r"(a2), "r"(a3), "r"(b0), "r"(b1));
}

/* ---------------- bias gather / mask pad (half, k-stride 344) ------------ */
__global__ void bias_gather_kernel(const float* __restrict__ table,
                                   const int* __restrict__ rel) {
    int i = blockIdx.x * blockDim.x + threadIdx.x;   // i = q*343 + k
    if (i >= N_TOK * N_TOK) return;
    int k = i % N_TOK;
    int q = i / N_TOK;
    int r = rel[i];
#pragma unroll
    for (int h = 0; h < HEADS; ++h)
        g_biasp[((size_t)h * PADQ + q) * PADK + k] = __float2half(table[r * HEADS + h]);
}

__global__ void mask_pad_kernel(const float* __restrict__ mask) {
    int idx = blockIdx.x * blockDim.x + threadIdx.x;  // (w*343 + q)*343 + k
    if (idx >= NWIN * N_TOK * N_TOK) return;
    int k = idx % N_TOK;
    int t = idx / N_TOK;
    int q = t % N_TOK;
    int w = t / N_TOK;
    g_maskp[((size_t)w * PADQ + q) * PADK + k] = __float2half(mask[idx]);
}

/* ------- fp16 warp-MMA GEMM core: 128x64 tile, 8 warps x 16 rows ----------
   As[row][chunk-words] stride 20, Bs likewise; fragment layout identical to
   the validated attention kernel (A = Qs pattern, B = Ks pattern).
   Accumulators c[8][4] cover rows {g, g+8} x cols {8ni+2t, +1}.            */
__device__ __forceinline__ void gemm_f16_core(uint32_t* As, uint32_t* Bs,
                                              float c[8][4], int mrow,
                                              int g, int t) {
#pragma unroll
    for (int ni = 0; ni < 8; ++ni)
#pragma unroll
        for (int e = 0; e < 4; ++e) c[ni][e] = 0.f;
    /* caller loops chunks; this does one chunk's mma */
}

/* ---------------- fused Q + KV projections (fp16 mma) -------------------- */
__global__ __launch_bounds__(256) void gemm_qkv_kernel(
    const float* __restrict__ x_in, const float* __restrict__ x_cross,
    const float* __restrict__ q_w, const float* __restrict__ kv_w) {
    __shared__ uint32_t As[128 * 20];
    __shared__ uint32_t Bs[64 * 20];
    const int tid = threadIdx.x;
    const int lane = tid & 31, warp = tid >> 5;
    const int g = lane >> 2, t = lane & 3;
    const int mrow = warp * 16;
    const int m0 = blockIdx.x * QT_ROWS;
    const int yt = blockIdx.y;
    const bool isq = (yt < 3);
    const float* A = isq ? x_in : x_cross;
    const float* W = isq ? q_w : kv_w;
    const int n0 = isq ? yt * 64 : (yt - 3) * 64;

    float c[8][4];
#pragma unroll
    for (int ni = 0; ni < 8; ++ni)
#pragma unroll
        for (int e = 0; e < 4; ++e) c[ni][e] = 0.f;

#pragma unroll 1
    for (int kt = 0; kt < 6; ++kt) {
        const int k0 = kt * 32;
        if (kt) __syncthreads();
        /* fill A [128 x 32] -> half words */
#pragma unroll
        for (int r = 0; r < 4; ++r) {
            int idx = tid + 256 * r;
            int row = idx >> 3, c4 = idx & 7;
            float4 v = *(const float4*)(A + (size_t)(m0 + row) * EMBED + k0 + c4 * 4);
            uint2 p;
            p.x = packh2(v.x, v.y);
            p.y = packh2(v.z, v.w);
            *(uint2*)(As + row * 20 + c4 * 2) = p;
        }
        /* fill B [64 x 32] */
#pragma unroll
        for (int r = 0; r < 2; ++r) {
            int idx = tid + 256 * r;
            int row = idx >> 3, c4 = idx & 7;
            float4 v = *(const float4*)(W + (size_t)(n0 + row) * EMBED + k0 + c4 * 4);
            uint2 p;
            p.x = packh2(v.x, v.y);
            p.y = packh2(v.z, v.w);
            *(uint2*)(Bs + row * 20 + c4 * 2) = p;
        }
        __syncthreads();
#pragma unroll
        for (int ks = 0; ks < 2; ++ks) {
            uint32_t a0 = As[(mrow + g) * 20 + 8 * ks + t];
            uint32_t a1 = As[(mrow + 8 + g) * 20 + 8 * ks + t];
            uint32_t a2 = As[(mrow + g) * 20 + 8 * ks + t + 4];
            uint32_t a3 = As[(mrow + 8 + g) * 20 + 8 * ks + t + 4];
#pragma unroll
            for (int ni = 0; ni < 8; ++ni) {
                uint32_t b0 = Bs[(8 * ni + g) * 20 + 8 * ks + t];
                uint32_t b1 = Bs[(8 * ni + g) * 20 + 8 * ks + t + 4];
                mma_f16(c[ni], a0, a1, a2, a3, b0, b1);
            }
        }
    }

    /* direct fragment scatter (half2 stores) */
    int r0 = m0 + mrow + g, r1 = r0 + 8;
    int bb0 = r0 / N_TOK, nn0 = r0 - bb0 * N_TOK;
    int bb1 = r1 / N_TOK, nn1 = r1 - bb1 * N_TOK;
#pragma unroll
    for (int ni = 0; ni < 8; ++ni) {
        int col = n0 + 8 * ni + 2 * t;
        if (isq) {
            int hh = col >> 5, d = col & 31;
            *(uint32_t*)(g_q + ((size_t)(bb0 * HEADS + hh) * N_TOK + nn0) * HD + d) =
                packh2(c[ni][0] * QSCALE, c[ni][1] * QSCALE);
            *(uint32_t*)(g_q + ((size_t)(bb1 * HEADS + hh) * N_TOK + nn1) * HD + d) =
                packh2(c[ni][2] * QSCALE, c[ni][3] * QSCALE);
        } else {
            int nc = (col < EMBED) ? col : col - EMBED;
            __half* dst = (col < EMBED) ? g_k : g_v;
            int hh = nc >> 5, d = nc & 31;
            *(uint32_t*)(dst + ((size_t)(bb0 * HEADS + hh) * N_TOK + nn0) * HD + d) =
                packh2(c[ni][0], c[ni][1]);
            *(uint32_t*)(dst + ((size_t)(bb1 * HEADS + hh) * N_TOK + nn1) * HD + d) =
                packh2(c[ni][2], c[ni][3]);
        }
    }
}

/* ---------------- output projection (fp16 mma, A = half ctx) ------------- */
__global__ __launch_bounds__(256) void gemm_proj_kernel(
    const float* __restrict__ proj_w, const float* __restrict__ proj_b,
    float* __restrict__ out) {
    __shared__ uint32_t As[128 * 20];
    __shared__ uint32_t Bs[64 * 20];
    const int tid = threadIdx.x;
    const int lane = tid & 31, warp = tid >> 5;
    const int g = lane >> 2, t = lane & 3;
    const int mrow = warp * 16;
    const int m0 = blockIdx.x * QT_ROWS;
    const int n0 = blockIdx.y * 64;

    float c[8][4];
#pragma unroll
    for (int ni = 0; ni < 8; ++ni)
#pragma unroll
        for (int e = 0; e < 4; ++e) c[ni][e] = 0.f;

#pragma unroll 1
    for (int kt = 0; kt < 6; ++kt) {
        const int k0 = kt * 32;
        if (kt) __syncthreads();
#pragma unroll
        for (int r = 0; r < 4; ++r) {
            int idx = tid + 256 * r;
            int row = idx >> 3, c4 = idx & 7;
            *(uint2*)(As + row * 20 + c4 * 2) =
                *(const uint2*)(g_ctx + (size_t)(m0 + row) * EMBED + k0 + c4 * 4);
        }
#pragma unroll
        for (int r = 0; r < 2; ++r) {
            int idx = tid + 256 * r;
            int row = idx >> 3, c4 = idx & 7;
            float4 v = *(const float4*)(proj_w + (size_t)(n0 + row) * EMBED + k0 + c4 * 4);
            uint2 p;
            p.x = packh2(v.x, v.y);
            p.y = packh2(v.z, v.w);
            *(uint2*)(Bs + row * 20 + c4 * 2) = p;
        }
        __syncthreads();
#pragma unroll
        for (int ks = 0; ks < 2; ++ks) {
            uint32_t a0 = As[(mrow + g) * 20 + 8 * ks + t];
            uint32_t a1 = As[(mrow + 8 + g) * 20 + 8 * ks + t];
            uint32_t a2 = As[(mrow + g) * 20 + 8 * ks + t + 4];
            uint32_t a3 = As[(mrow + 8 + g) * 20 + 8 * ks + t + 4];
#pragma unroll
            for (int ni = 0; ni < 8; ++ni) {
                uint32_t b0 = Bs[(8 * ni + g) * 20 + 8 * ks + t];
                uint32_t b1 = Bs[(8 * ni + g) * 20 + 8 * ks + t + 4];
                mma_f16(c[ni], a0, a1, a2, a3, b0, b1);
            }
        }
    }

    int r0 = m0 + mrow + g, r1 = r0 + 8;
#pragma unroll
    for (int ni = 0; ni < 8; ++ni) {
        int col = n0 + 8 * ni + 2 * t;
        float2 pb = *(const float2*)(proj_b + col);
        *(float2*)(out + (size_t)r0 * EMBED + col) =
            make_float2(c[ni][0] + pb.x, c[ni][1] + pb.y);
        *(float2*)(out + (size_t)r1 * EMBED + col) =
            make_float2(c[ni][2] + pb.x, c[ni][3] + pb.y);
    }
}

/* ---------------- fp16 register-resident flash attention ------------------ */
__global__ __launch_bounds__(256, 2) void attn_fp16_kernel() {
    __shared__ uint32_t Qs[128 * 20];   /* [row][d-pair], stride 20 words */
    __shared__ uint32_t Ks[64 * 20];    /* [tok][d-pair] */
    __shared__ uint32_t Vs[32 * 36];    /* [d][tok-pair], stride 36 */

    const int bid = blockIdx.x;
    const int qt = bid % NQT3;
    const int bh = bid / NQT3;
    const int b  = bh / HEADS;
    const int h  = bh - b * HEADS;
    const int w  = b & (NWIN - 1);
    const int q0 = qt * QT_ROWS;

    const int tid = threadIdx.x;
    const int lane = tid & 31, warp = tid >> 5;
    const int g = lane >> 2, t = lane & 3;
    const int mrow = warp * 16;

    const __half* Qg = g_q + (size_t)bh * N_TOK * HD;
    const __half* Kg = g_k + (size_t)bh * N_TOK * HD;
    const __half* Vg = g_v + (size_t)bh * N_TOK * HD;

    const int qrow0 = q0 + mrow + g;
    const __half* br0 = g_biasp + ((size_t)h * PADQ + qrow0) * PADK;
    const __half* br1 = br0 + 8 * PADK;
    const __half* mr0 = g_maskp + ((size_t)w * PADQ + qrow0) * PADK;
    const __half* mr1 = mr0 + 8 * PADK;

    /* Q tile [128x32] -> Qs (zero-pad rows >= N_TOK); direct half copy */
#pragma unroll
    for (int r = 0; r < 4; ++r) {
        int idx = tid + 256 * r;
        int row = idx >> 3, c4 = idx & 7;
        int qg = q0 + row;
        uint2 p = (qg < N_TOK) ? *(const uint2*)(Qg + (size_t)qg * HD + c4 * 4)
                               : make_uint2(0u, 0u);
        *(uint2*)(Qs + row * 20 + c4 * 2) = p;
    }
    __syncthreads();

    uint32_t qa[2][4];
#pragma unroll
    for (int ks = 0; ks < 2; ++ks) {
        qa[ks][0] = Qs[(mrow + g) * 20 + 8 * ks + t];
        qa[ks][1] = Qs[(mrow + 8 + g) * 20 + 8 * ks + t];
        qa[ks][2] = Qs[(mrow + g) * 20 + 8 * ks + t + 4];
        qa[ks][3] = Qs[(mrow + 8 + g) * 20 + 8 * ks + t + 4];
    }

    float m0r = -1e30f, m1r = -1e30f, l0 = 0.f, l1 = 0.f;
    float o[4][4];
#pragma unroll
    for (int nd = 0; nd < 4; ++nd)
#pragma unroll
        for (int e = 0; e < 4; ++e) o[nd][e] = 0.f;

#pragma unroll 1
    for (int kt = 0; kt < NKT; ++kt) {
        const int k0 = kt * 64;
        __syncthreads();

        /* K fill [64x32] direct half copy */
#pragma unroll
        for (int r = 0; r < 2; ++r) {
            int idx = tid + 256 * r;
            int row = idx >> 3, c4 = idx & 7;
            int kg = k0 + row;
            uint2 p = (kg < N_TOK) ? *(const uint2*)(Kg + (size_t)kg * HD + c4 * 4)
                                   : make_uint2(0u, 0u);
            *(uint2*)(Ks + row * 20 + c4 * 2) = p;
        }
        /* V fill transposed [d][tok-pair] */
        {
            int d = tid & 31;
            int seg = tid >> 5;
            __half vv[8];
#pragma unroll
            for (int s = 0; s < 8; ++s) {
                int kg = k0 + seg * 8 + s;
                vv[s] = (kg < N_TOK) ? Vg[(size_t)kg * HD + d] : __ushort_as_half(0);
            }
#pragma unroll
            for (int p = 0; p < 4; ++p)
                Vs[d * 36 + seg * 4 + p] = h2pack(vv[2 * p], vv[2 * p + 1]);
        }
        __syncthreads();

        /* S = Q K^T */
        float c[8][4];
#pragma unroll
        for (int ni = 0; ni < 8; ++ni)
#pragma unroll
            for (int e = 0; e < 4; ++e) c[ni][e] = 0.f;
#pragma unroll
        for (int ks = 0; ks < 2; ++ks)
#pragma unroll
            for (int ni = 0; ni < 8; ++ni) {
                uint32_t b0 = Ks[(8 * ni + g) * 20 + 8 * ks + t];
                uint32_t b1 = Ks[(8 * ni + g) * 20 + 8 * ks + t + 4];
                mma_f16(c[ni], qa[ks][0], qa[ks][1], qa[ks][2], qa[ks][3], b0, b1);
            }

        /* bias + mask (half2 loads; padded rows safe) */
        if (kt < NKT - 1) {
#pragma unroll
            for (int ni = 0; ni < 8; ++ni) {
                int off = k0 + 8 * ni + 2 * t;
                float2 b0v = __half22float2(*(const __half2*)(br0 + off));
                float2 m0v = __half22float2(*(const __half2*)(mr0 + off));
                float2 b1v = __half22float2(*(const __half2*)(br1 + off));
                float2 m1v = __half22float2(*(const __half2*)(mr1 + off));
                c[ni][0] += b0v.x + m0v.x;
                c[ni][1] += b0v.y + m0v.y;
                c[ni][2] += b1v.x + m1v.x;
                c[ni][3] += b1v.y + m1v.y;
            }
        } else {
#pragma unroll
            for (int ni = 0; ni < 8; ++ni) {
                int col = k0 + 8 * ni + 2 * t;
                if (col < N_TOK) {
                    c[ni][0] += __half2float(br0[col]) + __half2float(mr0[col]);
                    c[ni][2] += __half2float(br1[col]) + __half2float(mr1[col]);
                } else { c[ni][0] = -1e30f; c[ni][2] = -1e30f; }
                if (col + 1 < N_TOK) {
                    c[ni][1] += __half2float(br0[col + 1]) + __half2float(mr0[col + 1]);
                    c[ni][3] += __half2float(br1[col + 1]) + __half2float(mr1[col + 1]);
                } else { c[ni][1] = -1e30f; c[ni][3] = -1e30f; }
            }
        }

        /* register softmax */
        float mx0 = -1e30f, mx1 = -1e30f;
#pragma unroll
        for (int ni = 0; ni < 8; ++ni) {
            mx0 = fmaxf(mx0, fmaxf(c[ni][0], c[ni][1]));
            mx1 = fmaxf(mx1, fmaxf(c[ni][2], c[ni][3]));
        }
        mx0 = fmaxf(mx0, __shfl_xor_sync(0xFFFFFFFFu, mx0, 1));
        mx0 = fmaxf(mx0, __shfl_xor_sync(0xFFFFFFFFu, mx0, 2));
        mx1 = fmaxf(mx1, __shfl_xor_sync(0xFFFFFFFFu, mx1, 1));
        mx1 = fmaxf(mx1, __shfl_xor_sync(0xFFFFFFFFu, mx1, 2));
        float newm0 = fmaxf(m0r, mx0), newm1 = fmaxf(m1r, mx1);
        float alpha0 = __expf(m0r - newm0), alpha1 = __expf(m1r - newm1);
        m0r = newm0; m1r = newm1;

        uint32_t paL[8], paH[8];
        float sum0 = 0.f, sum1 = 0.f;
#pragma unroll
        for (int ni = 0; ni < 8; ++ni) {
            float p0 = __expf(c[ni][0] - newm0);
            float p1 = __expf(c[ni][1] - newm0);
            float p2 = __expf(c[ni][2] - newm1);
            float p3 = __expf(c[ni][3] - newm1);
            sum0 += p0 + p1;
            sum1 += p2 + p3;
            paL[ni] = packh2(p0, p1);
            paH[ni] = packh2(p2, p3);
        }
        sum0 += __shfl_xor_sync(0xFFFFFFFFu, sum0, 1);
        sum0 += __shfl_xor_sync(0xFFFFFFFFu, sum0, 2);
        sum1 += __shfl_xor_sync(0xFFFFFFFFu, sum1, 1);
        sum1 += __shfl_xor_sync(0xFFFFFFFFu, sum1, 2);
        l0 = l0 * alpha0 + sum0;
        l1 = l1 * alpha1 + sum1;

        /* O = alpha*O + P @ V */
#pragma unroll
        for (int nd = 0; nd < 4; ++nd) {
            o[nd][0] *= alpha0; o[nd][1] *= alpha0;
            o[nd][2] *= alpha1; o[nd][3] *= alpha1;
        }
#pragma unroll
        for (int kk = 0; kk < 4; ++kk)
#pragma unroll
            for (int nd = 0; nd < 4; ++nd) {
                uint32_t b0 = Vs[(8 * nd + g) * 36 + 8 * kk + t];
                uint32_t b1 = Vs[(8 * nd + g) * 36 + 8 * kk + t + 4];
                mma_f16(o[nd], paL[2 * kk], paH[2 * kk],
                        paL[2 * kk + 1], paH[2 * kk + 1], b0, b1);
            }
    }

    /* epilogue: normalize + write half ctx */
    float inv0 = __fdividef(1.f, l0);
    float inv1 = __fdividef(1.f, l1);
    int r0g = qrow0, r1g = qrow0 + 8;
#pragma unroll
    for (int nd = 0; nd < 4; ++nd) {
        int col = h * HD + 8 * nd + 2 * t;
        if (r0g < N_TOK)
            *(uint32_t*)(g_ctx + ((size_t)b * N_TOK + r0g) * EMBED + col) =
                packh2(o[nd][0] * inv0, o[nd][1] * inv0);
        if (r1g < N_TOK)
            *(uint32_t*)(g_ctx + ((size_t)b * N_TOK + r1g) * EMBED + col) =
                packh2(o[nd][2] * inv1, o[nd][3] * inv1);
    }
}

/* ---------------- launch -------------------------------------------------- */
extern "C" void kernel_launch(void* const* d_in, const int* in_sizes, int n_in,
                              void* d_out, int out_size) {
    const float* x_in    = (const float*)d_in[0];
    const float* x_cross = (const float*)d_in[1];
    const float* mask    = (const float*)d_in[2];
    const float* q_w     = (const float*)d_in[3];
    const float* kv_w    = (const float*)d_in[4];
    const float* proj_w  = (const float*)d_in[5];
    const float* proj_b  = (const float*)d_in[6];
    const float* table   = (const float*)d_in[7];
    const int*   rel     = (const int*)d_in[8];
    float* out = (float*)d_out;

    bias_gather_kernel<<<(N_TOK * N_TOK + 255) / 256, 256>>>(table, rel);
    mask_pad_kernel<<<(NWIN * N_TOK * N_TOK + 255) / 256, 256>>>(mask);
    gemm_qkv_kernel<<<dim3(M_ROWS / QT_ROWS, 9), 256>>>(x_in, x_cross, q_w, kv_w);
    attn_fp16_kernel<<<BATCH * HEADS * NQT3, 256>>>();
    gemm_proj_kernel<<<dim3(M_ROWS / QT_ROWS, 3), 256>>>(proj_w, proj_b, out);
}

// round 10
// speedup vs baseline: 5.4772x; 1.1901x over previous
#include <cuda_runtime.h>
#include <cuda_fp16.h>
#include <cstdint>

#define N_TOK 343
#define EMBED 192
#define HEADS 6
#define HD 32
#define BATCH 256
#define NWIN 64
#define QSCALE 0.17677669529663687f  /* 32^-0.5 */

#define M_ROWS (BATCH * N_TOK)        /* 87808 = 686*128 */
#define NKT 6                          /* 384 = 6*64 k tiles */
#define QT_ROWS 128
#define NQT3 3                         /* ceil(343/128) */
#define PADK 344
#define PADQ 384

/* GEMM dynamic smem: As 128x100 words + Bs 64x100 words */
#define GAS 100
#define SMEM_GEMM ((128 * GAS + 64 * GAS) * 4)   /* 76800 B */

/* ---------------- scratch (device globals) ------------------------------- */
__device__ __half g_q[BATCH * HEADS * N_TOK * HD];
__device__ __half g_k[BATCH * HEADS * N_TOK * HD];
__device__ __half g_v[BATCH * HEADS * N_TOK * HD];
__device__ __half g_ctx[BATCH * N_TOK * EMBED];
__device__ __half g_biasp[HEADS * PADQ * PADK];
__device__ __half g_maskp[NWIN * PADQ * PADK];

/* ---------------- helpers ------------------------------------------------- */
__device__ __forceinline__ uint32_t packh2(float lo, float hi) {
    uint32_t r;
    asm("cvt.rn.f16x2.f32 %0, %2, %1;" : "=r"(r) : "f"(lo), "f"(hi));
    return r;
}
__device__ __forceinline__ uint32_t h2pack(__half lo, __half hi) {
    return (uint32_t)__half_as_ushort(lo) | ((uint32_t)__half_as_ushort(hi) << 16);
}
__device__ __forceinline__ void mma_f16(float c[4],
                                        uint32_t a0, uint32_t a1,
                                        uint32_t a2, uint32_t a3,
                                        uint32_t b0, uint32_t b1) {
    asm volatile(
        "mma.sync.aligned.m16n8k16.row.col.f32.f16.f16.f32 "
        "{%0,%1,%2,%3}, {%4,%5,%6,%7}, {%8,%9}, {%0,%1,%2,%3};"
        : "+f"(c[0]), "+f"(c[1]), "+f"(c[2]), "+f"(c[3])
        : "r"(a0), "r"(a1), "r"(a2), "r"(a3), "r"(b0), "r"(b1));
}

/* ---------------- bias gather / mask pad ---------------------------------- */
__global__ void bias_gather_kernel(const float* __restrict__ table,
                                   const int* __restrict__ rel) {
    int i = blockIdx.x * blockDim.x + threadIdx.x;   // i = q*343 + k
    if (i >= N_TOK * N_TOK) return;
    int k = i % N_TOK;
    int q = i / N_TOK;
    int r = rel[i];
#pragma unroll
    for (int h = 0; h < HEADS; ++h)
        g_biasp[((size_t)h * PADQ + q) * PADK + k] = __float2half(table[r * HEADS + h]);
}

__global__ void mask_pad_kernel(const float* __restrict__ mask) {
    int idx = blockIdx.x * blockDim.x + threadIdx.x;
    if (idx >= NWIN * N_TOK * N_TOK) return;
    int k = idx % N_TOK;
    int t = idx / N_TOK;
    int q = t % N_TOK;
    int w = t / N_TOK;
    g_maskp[((size_t)w * PADQ + q) * PADK + k] = __float2half(mask[idx]);
}

/* ---------------- fused Q + KV projections (A-resident, 3 N-tiles) ------- */
__global__ __launch_bounds__(256) void gemm_qkv_kernel(
    const float* __restrict__ x_in, const float* __restrict__ x_cross,
    const float* __restrict__ q_w, const float* __restrict__ kv_w) {
    extern __shared__ uint32_t dynsm[];
    uint32_t* As = dynsm;                 /* [128][GAS] */
    uint32_t* Bs = dynsm + 128 * GAS;     /* [64][GAS]  */
    const int tid = threadIdx.x;
    const int lane = tid & 31, warp = tid >> 5;
    const int g = lane >> 2, t = lane & 3;
    const int mrow = warp * 16;
    const int m0 = blockIdx.x * QT_ROWS;
    const int yt = blockIdx.y;            /* 0: Q, 1: KV lo, 2: KV hi */
    const bool isq = (yt == 0);
    const float* A = isq ? x_in : x_cross;
    const float* W = isq ? q_w : kv_w;
    const int ntbase = (yt == 2) ? 3 : 0;

    /* fill A slab [128 x 192] once */
#pragma unroll 4
    for (int r = 0; r < 24; ++r) {
        int idx = tid + 256 * r;
        int row = idx / 48, c4 = idx % 48;
        float4 v = *(const float4*)(A + (size_t)(m0 + row) * EMBED + c4 * 4);
        uint2 p;
        p.x = packh2(v.x, v.y);
        p.y = packh2(v.z, v.w);
        *(uint2*)(As + row * GAS + c4 * 2) = p;
    }

    const int r0 = m0 + mrow + g, r1 = r0 + 8;
    const int bb0 = r0 / N_TOK, nn0 = r0 - bb0 * N_TOK;
    const int bb1 = r1 / N_TOK, nn1 = r1 - bb1 * N_TOK;

#pragma unroll 1
    for (int nt = 0; nt < 3; ++nt) {
        const int n0 = (ntbase + nt) * 64;
        if (nt) __syncthreads();
        /* fill B tile [64 x 192] */
#pragma unroll 4
        for (int r = 0; r < 12; ++r) {
            int idx = tid + 256 * r;
            int row = idx / 48, c4 = idx % 48;
            float4 v = *(const float4*)(W + (size_t)(n0 + row) * EMBED + c4 * 4);
            uint2 p;
            p.x = packh2(v.x, v.y);
            p.y = packh2(v.z, v.w);
            *(uint2*)(Bs + row * GAS + c4 * 2) = p;
        }
        __syncthreads();

        float c[8][4];
#pragma unroll
        for (int ni = 0; ni < 8; ++ni)
#pragma unroll
            for (int e = 0; e < 4; ++e) c[ni][e] = 0.f;
#pragma unroll
        for (int ks = 0; ks < 12; ++ks) {
            uint32_t a0 = As[(mrow + g) * GAS + 8 * ks + t];
            uint32_t a1 = As[(mrow + 8 + g) * GAS + 8 * ks + t];
            uint32_t a2 = As[(mrow + g) * GAS + 8 * ks + t + 4];
            uint32_t a3 = As[(mrow + 8 + g) * GAS + 8 * ks + t + 4];
#pragma unroll
            for (int ni = 0; ni < 8; ++ni) {
                uint32_t b0 = Bs[(8 * ni + g) * GAS + 8 * ks + t];
                uint32_t b1 = Bs[(8 * ni + g) * GAS + 8 * ks + t + 4];
                mma_f16(c[ni], a0, a1, a2, a3, b0, b1);
            }
        }

        /* scatter */
#pragma unroll
        for (int ni = 0; ni < 8; ++ni) {
            int col = n0 + 8 * ni + 2 * t;
            if (isq) {
                int hh = col >> 5, d = col & 31;
                *(uint32_t*)(g_q + ((size_t)(bb0 * HEADS + hh) * N_TOK + nn0) * HD + d) =
                    packh2(c[ni][0] * QSCALE, c[ni][1] * QSCALE);
                *(uint32_t*)(g_q + ((size_t)(bb1 * HEADS + hh) * N_TOK + nn1) * HD + d) =
                    packh2(c[ni][2] * QSCALE, c[ni][3] * QSCALE);
            } else {
                int nc = (col < EMBED) ? col : col - EMBED;
                __half* dst = (col < EMBED) ? g_k : g_v;
                int hh = nc >> 5, d = nc & 31;
                *(uint32_t*)(dst + ((size_t)(bb0 * HEADS + hh) * N_TOK + nn0) * HD + d) =
                    packh2(c[ni][0], c[ni][1]);
                *(uint32_t*)(dst + ((size_t)(bb1 * HEADS + hh) * N_TOK + nn1) * HD + d) =
                    packh2(c[ni][2], c[ni][3]);
            }
        }
    }
}

/* ---------------- output projection (A-resident, 3 N-tiles) --------------- */
__global__ __launch_bounds__(256) void gemm_proj_kernel(
    const float* __restrict__ proj_w, const float* __restrict__ proj_b,
    float* __restrict__ out) {
    extern __shared__ uint32_t dynsm[];
    uint32_t* As = dynsm;
    uint32_t* Bs = dynsm + 128 * GAS;
    const int tid = threadIdx.x;
    const int lane = tid & 31, warp = tid >> 5;
    const int g = lane >> 2, t = lane & 3;
    const int mrow = warp * 16;
    const int m0 = blockIdx.x * QT_ROWS;

    /* fill A slab from half ctx (raw copy) */
#pragma unroll 4
    for (int r = 0; r < 24; ++r) {
        int idx = tid + 256 * r;
        int row = idx / 48, c4 = idx % 48;
        *(uint2*)(As + row * GAS + c4 * 2) =
            *(const uint2*)(g_ctx + (size_t)(m0 + row) * EMBED + c4 * 4);
    }

    const int r0 = m0 + mrow + g, r1 = r0 + 8;

#pragma unroll 1
    for (int nt = 0; nt < 3; ++nt) {
        const int n0 = nt * 64;
        if (nt) __syncthreads();
#pragma unroll 4
        for (int r = 0; r < 12; ++r) {
            int idx = tid + 256 * r;
            int row = idx / 48, c4 = idx % 48;
            float4 v = *(const float4*)(proj_w + (size_t)(n0 + row) * EMBED + c4 * 4);
            uint2 p;
            p.x = packh2(v.x, v.y);
            p.y = packh2(v.z, v.w);
            *(uint2*)(Bs + row * GAS + c4 * 2) = p;
        }
        __syncthreads();

        float c[8][4];
#pragma unroll
        for (int ni = 0; ni < 8; ++ni)
#pragma unroll
            for (int e = 0; e < 4; ++e) c[ni][e] = 0.f;
#pragma unroll
        for (int ks = 0; ks < 12; ++ks) {
            uint32_t a0 = As[(mrow + g) * GAS + 8 * ks + t];
            uint32_t a1 = As[(mrow + 8 + g) * GAS + 8 * ks + t];
            uint32_t a2 = As[(mrow + g) * GAS + 8 * ks + t + 4];
            uint32_t a3 = As[(mrow + 8 + g) * GAS + 8 * ks + t + 4];
#pragma unroll
            for (int ni = 0; ni < 8; ++ni) {
                uint32_t b0 = Bs[(8 * ni + g) * GAS + 8 * ks + t];
                uint32_t b1 = Bs[(8 * ni + g) * GAS + 8 * ks + t + 4];
                mma_f16(c[ni], a0, a1, a2, a3, b0, b1);
            }
        }

#pragma unroll
        for (int ni = 0; ni < 8; ++ni) {
            int col = n0 + 8 * ni + 2 * t;
            float2 pb = *(const float2*)(proj_b + col);
            *(float2*)(out + (size_t)r0 * EMBED + col) =
                make_float2(c[ni][0] + pb.x, c[ni][1] + pb.y);
            *(float2*)(out + (size_t)r1 * EMBED + col) =
                make_float2(c[ni][2] + pb.x, c[ni][3] + pb.y);
        }
    }
}

/* ---------------- fp16 flash attention, double-buffered K/V --------------- */
__global__ __launch_bounds__(256, 2) void attn_fp16_kernel() {
    __shared__ uint32_t Qs[128 * 20];
    __shared__ uint32_t Ks[2][64 * 20];
    __shared__ uint32_t Vs[2][32 * 36];

    const int bid = blockIdx.x;
    const int qt = bid % NQT3;
    const int bh = bid / NQT3;
    const int b  = bh / HEADS;
    const int h  = bh - b * HEADS;
    const int w  = b & (NWIN - 1);
    const int q0 = qt * QT_ROWS;

    const int tid = threadIdx.x;
    const int lane = tid & 31, warp = tid >> 5;
    const int g = lane >> 2, t = lane & 3;
    const int mrow = warp * 16;

    const __half* Qg = g_q + (size_t)bh * N_TOK * HD;
    const __half* Kg = g_k + (size_t)bh * N_TOK * HD;
    const __half* Vg = g_v + (size_t)bh * N_TOK * HD;

    const int qrow0 = q0 + mrow + g;
    const __half* br0 = g_biasp + ((size_t)h * PADQ + qrow0) * PADK;
    const __half* br1 = br0 + 8 * PADK;
    const __half* mr0 = g_maskp + ((size_t)w * PADQ + qrow0) * PADK;
    const __half* mr1 = mr0 + 8 * PADK;

    /* per-thread fill coordinates */
    const int krow0 = tid >> 3, kc40 = tid & 7;
    const int krow1 = (tid + 256) >> 3, kc41 = tid & 7;   /* idx+256: same c4 */
    const int vd = tid & 31, vseg = tid >> 5;

    /* Q fill [128x32] */
#pragma unroll
    for (int r = 0; r < 4; ++r) {
        int idx = tid + 256 * r;
        int row = idx >> 3, c4 = idx & 7;
        int qg = q0 + row;
        uint2 p = (qg < N_TOK) ? *(const uint2*)(Qg + (size_t)qg * HD + c4 * 4)
                               : make_uint2(0u, 0u);
        *(uint2*)(Qs + row * 20 + c4 * 2) = p;
    }

    /* prefetch tile 0 into regs, store buf 0 */
    uint2 ka, kb;
    uint32_t vr[4];
    {
        const int k0 = 0;
        int kg0 = k0 + krow0;
        ka = (kg0 < N_TOK) ? *(const uint2*)(Kg + (size_t)kg0 * HD + kc40 * 4)
                           : make_uint2(0u, 0u);
        int kg1 = k0 + krow1;
        kb = (kg1 < N_TOK) ? *(const uint2*)(Kg + (size_t)kg1 * HD + kc41 * 4)
                           : make_uint2(0u, 0u);
#pragma unroll
        for (int p = 0; p < 4; ++p) {
            int kga = k0 + vseg * 8 + 2 * p;
            __half va = (kga < N_TOK) ? Vg[(size_t)kga * HD + vd] : __ushort_as_half(0);
            __half vb = (kga + 1 < N_TOK) ? Vg[(size_t)(kga + 1) * HD + vd] : __ushort_as_half(0);
            vr[p] = h2pack(va, vb);
        }
        *(uint2*)(&Ks[0][krow0 * 20 + kc40 * 2]) = ka;
        *(uint2*)(&Ks[0][krow1 * 20 + kc41 * 2]) = kb;
#pragma unroll
        for (int p = 0; p < 4; ++p) Vs[0][vd * 36 + vseg * 4 + p] = vr[p];
    }
    __syncthreads();

    /* Q A-fragments */
    uint32_t qa[2][4];
#pragma unroll
    for (int ks = 0; ks < 2; ++ks) {
        qa[ks][0] = Qs[(mrow + g) * 20 + 8 * ks + t];
        qa[ks][1] = Qs[(mrow + 8 + g) * 20 + 8 * ks + t];
        qa[ks][2] = Qs[(mrow + g) * 20 + 8 * ks + t + 4];
        qa[ks][3] = Qs[(mrow + 8 + g) * 20 + 8 * ks + t + 4];
    }

    float m0r = -1e30f, m1r = -1e30f, l0 = 0.f, l1 = 0.f;
    float o[4][4];
#pragma unroll
    for (int nd = 0; nd < 4; ++nd)
#pragma unroll
        for (int e = 0; e < 4; ++e) o[nd][e] = 0.f;

#pragma unroll 1
    for (int kt = 0; kt < NKT; ++kt) {
        const int cur = kt & 1;
        const bool pf = (kt + 1 < NKT);

        /* prefetch next tile into regs (LDG latency hidden under mma) */
        if (pf) {
            const int k0 = (kt + 1) * 64;
            int kg0 = k0 + krow0;
            ka = (kg0 < N_TOK) ? *(const uint2*)(Kg + (size_t)kg0 * HD + kc40 * 4)
                               : make_uint2(0u, 0u);
            int kg1 = k0 + krow1;
            kb = (kg1 < N_TOK) ? *(const uint2*)(Kg + (size_t)kg1 * HD + kc41 * 4)
                               : make_uint2(0u, 0u);
#pragma unroll
            for (int p = 0; p < 4; ++p) {
                int kga = k0 + vseg * 8 + 2 * p;
                __half va = (kga < N_TOK) ? Vg[(size_t)kga * HD + vd] : __ushort_as_half(0);
                __half vb = (kga + 1 < N_TOK) ? Vg[(size_t)(kga + 1) * HD + vd] : __ushort_as_half(0);
                vr[p] = h2pack(va, vb);
            }
        }

        const int k0 = kt * 64;
        const uint32_t* Kc = Ks[cur];
        const uint32_t* Vc = Vs[cur];

        /* S = Q K^T */
        float c[8][4];
#pragma unroll
        for (int ni = 0; ni < 8; ++ni)
#pragma unroll
            for (int e = 0; e < 4; ++e) c[ni][e] = 0.f;
#pragma unroll
        for (int ks = 0; ks < 2; ++ks)
#pragma unroll
            for (int ni = 0; ni < 8; ++ni) {
                uint32_t b0 = Kc[(8 * ni + g) * 20 + 8 * ks + t];
                uint32_t b1 = Kc[(8 * ni + g) * 20 + 8 * ks + t + 4];
                mma_f16(c[ni], qa[ks][0], qa[ks][1], qa[ks][2], qa[ks][3], b0, b1);
            }

        /* bias + mask */
        if (kt < NKT - 1) {
#pragma unroll
            for (int ni = 0; ni < 8; ++ni) {
                int off = k0 + 8 * ni + 2 * t;
                float2 b0v = __half22float2(*(const __half2*)(br0 + off));
                float2 m0v = __half22float2(*(const __half2*)(mr0 + off));
                float2 b1v = __half22float2(*(const __half2*)(br1 + off));
                float2 m1v = __half22float2(*(const __half2*)(mr1 + off));
                c[ni][0] += b0v.x + m0v.x;
                c[ni][1] += b0v.y + m0v.y;
                c[ni][2] += b1v.x + m1v.x;
                c[ni][3] += b1v.y + m1v.y;
            }
        } else {
#pragma unroll
            for (int ni = 0; ni < 8; ++ni) {
                int col = k0 + 8 * ni + 2 * t;
                if (col < N_TOK) {
                    c[ni][0] += __half2float(br0[col]) + __half2float(mr0[col]);
                    c[ni][2] += __half2float(br1[col]) + __half2float(mr1[col]);
                } else { c[ni][0] = -1e30f; c[ni][2] = -1e30f; }
                if (col + 1 < N_TOK) {
                    c[ni][1] += __half2float(br0[col + 1]) + __half2float(mr0[col + 1]);
                    c[ni][3] += __half2float(br1[col + 1]) + __half2float(mr1[col + 1]);
                } else { c[ni][1] = -1e30f; c[ni][3] = -1e30f; }
            }
        }

        /* register softmax */
        float mx0 = -1e30f, mx1 = -1e30f;
#pragma unroll
        for (int ni = 0; ni < 8; ++ni) {
            mx0 = fmaxf(mx0, fmaxf(c[ni][0], c[ni][1]));
            mx1 = fmaxf(mx1, fmaxf(c[ni][2], c[ni][3]));
        }
        mx0 = fmaxf(mx0, __shfl_xor_sync(0xFFFFFFFFu, mx0, 1));
        mx0 = fmaxf(mx0, __shfl_xor_sync(0xFFFFFFFFu, mx0, 2));
        mx1 = fmaxf(mx1, __shfl_xor_sync(0xFFFFFFFFu, mx1, 1));
        mx1 = fmaxf(mx1, __shfl_xor_sync(0xFFFFFFFFu, mx1, 2));
        float newm0 = fmaxf(m0r, mx0), newm1 = fmaxf(m1r, mx1);
        float alpha0 = __expf(m0r - newm0), alpha1 = __expf(m1r - newm1);
        m0r = newm0; m1r = newm1;

        uint32_t paL[8], paH[8];
        float sum0 = 0.f, sum1 = 0.f;
#pragma unroll
        for (int ni = 0; ni < 8; ++ni) {
            float p0 = __expf(c[ni][0] - newm0);
            float p1 = __expf(c[ni][1] - newm0);
            float p2 = __expf(c[ni][2] - newm1);
            float p3 = __expf(c[ni][3] - newm1);
            sum0 += p0 + p1;
            sum1 += p2 + p3;
            paL[ni] = packh2(p0, p1);
            paH[ni] = packh2(p2, p3);
        }
        sum0 += __shfl_xor_sync(0xFFFFFFFFu, sum0, 1);
        sum0 += __shfl_xor_sync(0xFFFFFFFFu, sum0, 2);
        sum1 += __shfl_xor_sync(0xFFFFFFFFu, sum1, 1);
        sum1 += __shfl_xor_sync(0xFFFFFFFFu, sum1, 2);
        l0 = l0 * alpha0 + sum0;
        l1 = l1 * alpha1 + sum1;

        /* O = alpha*O + P @ V */
#pragma unroll
        for (int nd = 0; nd < 4; ++nd) {
            o[nd][0] *= alpha0; o[nd][1] *= alpha0;
            o[nd][2] *= alpha1; o[nd][3] *= alpha1;
        }
#pragma unroll
        for (int kk = 0; kk < 4; ++kk)
#pragma unroll
            for (int nd = 0; nd < 4; ++nd) {
                uint32_t b0 = Vc[(8 * nd + g) * 36 + 8 * kk + t];
                uint32_t b1 = Vc[(8 * nd + g) * 36 + 8 * kk + t + 4];
                mma_f16(o[nd], paL[2 * kk], paH[2 * kk],
                        paL[2 * kk + 1], paH[2 * kk + 1], b0, b1);
            }

        /* store prefetched regs into the other buffer; one barrier/iter */
        if (pf) {
            *(uint2*)(&Ks[cur ^ 1][krow0 * 20 + kc40 * 2]) = ka;
            *(uint2*)(&Ks[cur ^ 1][krow1 * 20 + kc41 * 2]) = kb;
#pragma unroll
            for (int p = 0; p < 4; ++p) Vs[cur ^ 1][vd * 36 + vseg * 4 + p] = vr[p];
            __syncthreads();
        }
    }

    /* epilogue */
    float inv0 = __fdividef(1.f, l0);
    float inv1 = __fdividef(1.f, l1);
    int r0g = qrow0, r1g = qrow0 + 8;
#pragma unroll
    for (int nd = 0; nd < 4; ++nd) {
        int col = h * HD + 8 * nd + 2 * t;
        if (r0g < N_TOK)
            *(uint32_t*)(g_ctx + ((size_t)b * N_TOK + r0g) * EMBED + col) =
                packh2(o[nd][0] * inv0, o[nd][1] * inv0);
        if (r1g < N_TOK)
            *(uint32_t*)(g_ctx + ((size_t)b * N_TOK + r1g) * EMBED + col) =
                packh2(o[nd][2] * inv1, o[nd][3] * inv1);
    }
}

/* ---------------- launch -------------------------------------------------- */
extern "C" void kernel_launch(void* const* d_in, const int* in_sizes, int n_in,
                              void* d_out, int out_size) {
    const float* x_in    = (const float*)d_in[0];
    const float* x_cross = (const float*)d_in[1];
    const float* mask    = (const float*)d_in[2];
    const float* q_w     = (const float*)d_in[3];
    const float* kv_w    = (const float*)d_in[4];
    const float* proj_w  = (const float*)d_in[5];
    const float* proj_b  = (const float*)d_in[6];
    const float* table   = (const float*)d_in[7];
    const int*   rel     = (const int*)d_in[8];
    float* out = (float*)d_out;

    cudaFuncSetAttribute(gemm_qkv_kernel,
                         cudaFuncAttributeMaxDynamicSharedMemorySize, SMEM_GEMM);
    cudaFuncSetAttribute(gemm_proj_kernel,
                         cudaFuncAttributeMaxDynamicSharedMemorySize, SMEM_GEMM);

    bias_gather_kernel<<<(N_TOK * N_TOK + 255) / 256, 256>>>(table, rel);
    mask_pad_kernel<<<(NWIN * N_TOK * N_TOK + 255) / 256, 256>>>(mask);
    gemm_qkv_kernel<<<dim3(M_ROWS / QT_ROWS, 3), 256, SMEM_GEMM>>>(
        x_in, x_cross, q_w, kv_w);
    attn_fp16_kernel<<<BATCH * HEADS * NQT3, 256>>>();
    gemm_proj_kernel<<<M_ROWS / QT_ROWS, 256, SMEM_GEMM>>>(proj_w, proj_b, out);
}